// round 6
// baseline (speedup 1.0000x reference)
#include <cuda_runtime.h>
#include <cuda_bf16.h>
#include <math.h>
#include <stdint.h>

#define BB 2
#define SS 2048
#define DM 1024
#define NH 16
#define HD 64
#define NEG_INF -1000000000.0f

// ---------------- scratch (device globals: allocation-free) ----------------
__device__ float g_tq[BB*SS*DM];   // x@Wq  [B,S,Dm]
__device__ float g_tk[BB*SS*DM];
__device__ float g_tv[BB*SS*DM];

__device__ __nv_bfloat16 g_xhi[BB*SS*DM];       // activation split
__device__ __nv_bfloat16 g_xlo[BB*SS*DM];
__device__ __nv_bfloat16 g_wthi[4*DM*DM];       // W^T split: [z][N][K]
__device__ __nv_bfloat16 g_wtlo[4*DM*DM];

__device__ __nv_bfloat16 g_Qhi[BB*NH*SS*HD];    // [B,H,S,Hd], pre-scaled
__device__ __nv_bfloat16 g_Qlo[BB*NH*SS*HD];
__device__ __nv_bfloat16 g_Khi[BB*NH*SS*HD];
__device__ __nv_bfloat16 g_Klo[BB*NH*SS*HD];
__device__ __nv_bfloat16 g_Vthi[BB*NH*HD*SS];   // [B,H,Hd,S] (transposed)
__device__ __nv_bfloat16 g_Vtlo[BB*NH*HD*SS];

__device__ float g_cos[SS*32];
__device__ float g_sin[SS*32];

// ================= warp-MMA helpers (sm_103 base, no 'a' features) ==========
__device__ __forceinline__ uint32_t smem_u32(const void* p) {
    uint32_t a;
    asm("{ .reg .u64 t; cvta.to.shared.u64 t, %1; cvt.u32.u64 %0, t; }" : "=r"(a) : "l"(p));
    return a;
}
__device__ __forceinline__ void ldsm_x4(uint32_t* r, uint32_t addr) {
    asm volatile("ldmatrix.sync.aligned.m8n8.x4.shared.b16 {%0,%1,%2,%3}, [%4];"
                 : "=r"(r[0]), "=r"(r[1]), "=r"(r[2]), "=r"(r[3]) : "r"(addr));
}
__device__ __forceinline__ void mma_bf16(float* c, const uint32_t* a,
                                         uint32_t b0, uint32_t b1) {
    asm volatile(
        "mma.sync.aligned.m16n8k16.row.col.f32.bf16.bf16.f32 "
        "{%0,%1,%2,%3}, {%4,%5,%6,%7}, {%8,%9}, {%0,%1,%2,%3};"
        : "+f"(c[0]), "+f"(c[1]), "+f"(c[2]), "+f"(c[3])
        : "r"(a[0]), "r"(a[1]), "r"(a[2]), "r"(a[3]), "r"(b0), "r"(b1));
}
__device__ __forceinline__ uint32_t packh(__nv_bfloat16 a, __nv_bfloat16 b) {
    return ((uint32_t)__bfloat16_as_ushort(b) << 16) | (uint32_t)__bfloat16_as_ushort(a);
}
__device__ __forceinline__ void cp_async16(uint32_t saddr, const void* gaddr) {
    asm volatile("cp.async.cg.shared.global [%0], [%1], 16;"
                 :: "r"(saddr), "l"(gaddr) : "memory");
}
__device__ __forceinline__ void cp_commit() {
    asm volatile("cp.async.commit_group;" ::: "memory");
}
template<int N> __device__ __forceinline__ void cp_wait() {
    asm volatile("cp.async.wait_group %0;" :: "n"(N) : "memory");
}

// ================= split / weight-prep kernels ==============================
__global__ __launch_bounds__(256)
void split_kernel(const float* __restrict__ src,
                  __nv_bfloat16* __restrict__ hi,
                  __nv_bfloat16* __restrict__ lo)
{
    int i = (blockIdx.x * 256 + threadIdx.x) * 4;
    float4 v = *(const float4*)&src[i];
    __nv_bfloat16 h0 = __float2bfloat16(v.x);
    __nv_bfloat16 h1 = __float2bfloat16(v.y);
    __nv_bfloat16 h2 = __float2bfloat16(v.z);
    __nv_bfloat16 h3 = __float2bfloat16(v.w);
    __nv_bfloat16 l0 = __float2bfloat16(v.x - __bfloat162float(h0));
    __nv_bfloat16 l1 = __float2bfloat16(v.y - __bfloat162float(h1));
    __nv_bfloat16 l2 = __float2bfloat16(v.z - __bfloat162float(h2));
    __nv_bfloat16 l3 = __float2bfloat16(v.w - __bfloat162float(h3));
    *(__nv_bfloat162*)&hi[i]     = __nv_bfloat162(h0, h1);
    *(__nv_bfloat162*)&hi[i + 2] = __nv_bfloat162(h2, h3);
    *(__nv_bfloat162*)&lo[i]     = __nv_bfloat162(l0, l1);
    *(__nv_bfloat162*)&lo[i + 2] = __nv_bfloat162(l2, l3);
}

__global__ __launch_bounds__(256)
void wsplit_kernel(const float* __restrict__ Wq, const float* __restrict__ Wk,
                   const float* __restrict__ Wv, const float* __restrict__ Wo)
{
    __shared__ float tile[32][33];
    int z = blockIdx.z;
    const float* __restrict__ W = (z == 0) ? Wq : ((z == 1) ? Wk : ((z == 2) ? Wv : Wo));
    int n0 = blockIdx.x * 32;
    int k0 = blockIdx.y * 32;
    int tx = threadIdx.x & 31;
    int ty = threadIdx.x >> 5;
    #pragma unroll
    for (int i = 0; i < 4; i++) {
        int k = ty + i * 8;
        tile[k][tx] = W[(size_t)(k0 + k) * DM + n0 + tx];
    }
    __syncthreads();
    #pragma unroll
    for (int i = 0; i < 4; i++) {
        int n = ty + i * 8;
        float v = tile[tx][n];
        __nv_bfloat16 h = __float2bfloat16(v);
        __nv_bfloat16 l = __float2bfloat16(v - __bfloat162float(h));
        size_t di = ((size_t)z * DM + n0 + n) * DM + k0 + tx;
        g_wthi[di] = h;
        g_wtlo[di] = l;
    }
}

// ================= HMMA split-bf16 GEMM (512 thr, 2-stage cp.async) =========
#define GBM 128
#define GBN 128
#define GBK 32
#define GSTR 40
#define STB (GBM * GSTR * 2)          // bytes per array per stage = 10240
#define GSM_TOTAL (8 * STB)           // 2 stages x 4 arrays = 81920

__global__ __launch_bounds__(512)
void gemm_tc_kernel(const __nv_bfloat16* __restrict__ Ahi,
                    const __nv_bfloat16* __restrict__ Alo,
                    const __nv_bfloat16* __restrict__ Whi,
                    const __nv_bfloat16* __restrict__ Wlo,
                    float* __restrict__ C0, float* __restrict__ C1,
                    float* __restrict__ C2)
{
    extern __shared__ __align__(16) char dsm[];

    const int tid  = threadIdx.x;
    const int wid  = tid >> 5;
    const int lane = tid & 31;
    const int m0 = blockIdx.y * GBM;
    const int n0 = blockIdx.x * GBN;
    const int z  = blockIdx.z;
    const __nv_bfloat16* __restrict__ Wh = Whi + (size_t)z * DM * DM;
    const __nv_bfloat16* __restrict__ Wl = Wlo + (size_t)z * DM * DM;
    float* __restrict__ C = (z == 0) ? C0 : ((z == 1) ? C1 : C2);

    const int wm = wid & 3;        // 4 row slabs of 32
    const int wn = wid >> 2;       // 4 col slabs of 32

    const int row_off = (lane & 7) + ((lane >> 3) & 1) * 8;
    const int kadd    = ((lane >> 4) & 1) * 8;
    const uint32_t lmoff = (uint32_t)(row_off * (GSTR * 2) + kadd * 2);

    const uint32_t sbase = smem_u32(dsm);
    const int r_a = tid >> 2;      // 0..127
    const int c_a = tid & 3;       // 4 x 16B chunks
    const uint32_t so = (uint32_t)(r_a * (GSTR * 2) + c_a * 16);

    float acc[2][4][4];
    #pragma unroll
    for (int i = 0; i < 2; i++)
        #pragma unroll
        for (int j = 0; j < 4; j++)
            #pragma unroll
            for (int q = 0; q < 4; q++) acc[i][j][q] = 0.0f;

    const int NK = DM / GBK;   // 32

    // issue stage 0 loads
    {
        uint32_t s0 = sbase;
        size_t ga = (size_t)(m0 + r_a) * DM + c_a * 8;
        size_t gb = (size_t)(n0 + r_a) * DM + c_a * 8;
        cp_async16(s0 + so,           &Ahi[ga]);
        cp_async16(s0 + STB + so,     &Alo[ga]);
        cp_async16(s0 + 2*STB + so,   &Wh[gb]);
        cp_async16(s0 + 3*STB + so,   &Wl[gb]);
        cp_commit();
    }

    for (int kc = 0; kc < NK; kc++) {
        if (kc + 1 < NK) {
            const int k0 = (kc + 1) * GBK;
            uint32_t s0 = sbase + (uint32_t)(((kc + 1) & 1) * 4 * STB);
            size_t ga = (size_t)(m0 + r_a) * DM + k0 + c_a * 8;
            size_t gb = (size_t)(n0 + r_a) * DM + k0 + c_a * 8;
            cp_async16(s0 + so,           &Ahi[ga]);
            cp_async16(s0 + STB + so,     &Alo[ga]);
            cp_async16(s0 + 2*STB + so,   &Wh[gb]);
            cp_async16(s0 + 3*STB + so,   &Wl[gb]);
            cp_commit();
            cp_wait<1>();
        } else {
            cp_wait<0>();
        }
        __syncthreads();

        const uint32_t st = sbase + (uint32_t)((kc & 1) * 4 * STB);
        const uint32_t sAh_b = st;
        const uint32_t sAl_b = st + STB;
        const uint32_t sBh_b = st + 2 * STB;
        const uint32_t sBl_b = st + 3 * STB;

        #pragma unroll
        for (int ks = 0; ks < 2; ks++) {
            uint32_t ah[2][4], al[2][4];
            #pragma unroll
            for (int mt = 0; mt < 2; mt++) {
                uint32_t aoff = (uint32_t)((wm * 32 + mt * 16) * (GSTR * 2) + ks * 32) + lmoff;
                ldsm_x4(ah[mt], sAh_b + aoff);
                ldsm_x4(al[mt], sAl_b + aoff);
            }
            uint32_t bh[2][4], bl[2][4];
            #pragma unroll
            for (int nt2 = 0; nt2 < 2; nt2++) {
                uint32_t boff = (uint32_t)((wn * 32 + nt2 * 16) * (GSTR * 2) + ks * 32) + lmoff;
                ldsm_x4(bh[nt2], sBh_b + boff);
                ldsm_x4(bl[nt2], sBl_b + boff);
            }
            #pragma unroll
            for (int mt = 0; mt < 2; mt++) {
                #pragma unroll
                for (int nt = 0; nt < 4; nt++) {
                    int n2 = nt >> 1, od = nt & 1;
                    mma_bf16(acc[mt][nt], ah[mt], bh[n2][od], bh[n2][od + 2]);
                    mma_bf16(acc[mt][nt], ah[mt], bl[n2][od], bl[n2][od + 2]);
                    mma_bf16(acc[mt][nt], al[mt], bh[n2][od], bh[n2][od + 2]);
                }
            }
        }
        __syncthreads();
    }

    const int g   = lane >> 2;
    const int tig = lane & 3;
    #pragma unroll
    for (int mt = 0; mt < 2; mt++) {
        int row = m0 + wm * 32 + mt * 16 + g;
        #pragma unroll
        for (int nt = 0; nt < 4; nt++) {
            int col = n0 + wn * 32 + nt * 8 + tig * 2;
            *(float2*)&C[(size_t)row * DM + col]       = make_float2(acc[mt][nt][0], acc[mt][nt][1]);
            *(float2*)&C[(size_t)(row + 8) * DM + col] = make_float2(acc[mt][nt][2], acc[mt][nt][3]);
        }
    }
}

// ---------------- trig table (double precision, tiny) ----------------------
__global__ __launch_bounds__(256)
void trig_kernel()
{
    int idx = blockIdx.x * 256 + threadIdx.x;   // [0, SS*32)
    int s = idx >> 5, j = idx & 31;
    double inv = exp(-(double)j * (9.210340371976184 / 32.0));
    double ang = (double)s * inv;
    double sn, cs;
    sincos(ang, &sn, &cs);
    g_cos[idx] = (float)cs;
    g_sin[idx] = (float)sn;
}

// ---------------- RoPE + transpose + split: Q, K ----------------------------
__global__ __launch_bounds__(256)
void ropeqk_kernel()
{
    const int which = blockIdx.y;   // 0 = Q, 1 = K
    const float* __restrict__ src = (which == 0) ? g_tq : g_tk;
    __nv_bfloat16* __restrict__ dhi = (which == 0) ? g_Qhi : g_Khi;
    __nv_bfloat16* __restrict__ dlo = (which == 0) ? g_Qlo : g_Klo;
    const float scale = (which == 0) ? 0.125f : 1.0f;

    int idx = blockIdx.x * 256 + threadIdx.x;
    int j = idx & 31;
    int s = (idx >> 5) & (SS - 1);
    int h = (idx >> 16) & (NH - 1);
    int b = idx >> 20;

    size_t si = ((size_t)(b * SS + s)) * DM + h * HD;
    float t1 = src[si + j];
    float t2 = src[si + 32 + j];
    float c  = g_cos[s * 32 + j];
    float sn = g_sin[s * 32 + j];
    float o1 = (t1 * c - t2 * sn) * scale;
    float o2 = (t1 * sn + t2 * c) * scale;

    __nv_bfloat16 h1 = __float2bfloat16(o1);
    __nv_bfloat16 h2 = __float2bfloat16(o2);
    __nv_bfloat16 l1 = __float2bfloat16(o1 - __bfloat162float(h1));
    __nv_bfloat16 l2 = __float2bfloat16(o2 - __bfloat162float(h2));

    size_t di = (((size_t)(b * NH + h)) * SS + s) * HD;
    dhi[di + j]      = h1;
    dhi[di + 32 + j] = h2;
    dlo[di + j]      = l1;
    dlo[di + 32 + j] = l2;
}

// ---------------- V transpose + split: [B,S,Dm] -> [B,H,Hd,S] ---------------
__global__ __launch_bounds__(256)
void vtrans_kernel()
{
    __shared__ float tile[32][65];
    const int st = blockIdx.x;
    const int h  = blockIdx.y;
    const int b  = blockIdx.z;
    const int tid = threadIdx.x;

    const float* __restrict__ src = g_tv + ((size_t)(b * SS + st * 32)) * DM + h * HD;
    #pragma unroll
    for (int i = 0; i < 8; i++) {
        int idx = tid + i * 256;
        int r = idx >> 6, c = idx & 63;
        tile[r][c] = src[(size_t)r * DM + c];
    }
    __syncthreads();
    #pragma unroll
    for (int i = 0; i < 8; i++) {
        int idx = tid + i * 256;
        int c = idx >> 5, r = idx & 31;
        float v = tile[r][c];
        __nv_bfloat16 hh = __float2bfloat16(v);
        __nv_bfloat16 ll = __float2bfloat16(v - __bfloat162float(hh));
        size_t di = ((size_t)(b * NH + h) * HD + c) * SS + st * 32 + r;
        g_Vthi[di] = hh;
        g_Vtlo[di] = ll;
    }
}

// ---------------- HMMA split-bf16 flash attention ---------------------------
#define ASTR 72

__global__ __launch_bounds__(128)
void attention_tc_kernel(const float* __restrict__ mask)
{
    __shared__ __align__(16) __nv_bfloat16 sKh[64 * ASTR];
    __shared__ __align__(16) __nv_bfloat16 sKl[64 * ASTR];
    __shared__ __align__(16) __nv_bfloat16 sVh[64 * ASTR];
    __shared__ __align__(16) __nv_bfloat16 sVl[64 * ASTR];
    __shared__ float madd[64];

    const int tid  = threadIdx.x;
    const int wid  = tid >> 5;
    const int lane = tid & 31;
    const int qt = gridDim.x - 1 - blockIdx.x;
    const int bh = blockIdx.y;
    const int b  = bh >> 4;
    const int h  = bh & 15;

    const size_t baseqk = (size_t)bh * SS * HD;
    const size_t basev  = (size_t)bh * HD * SS;

    const int row_off = (lane & 7) + ((lane >> 3) & 1) * 8;
    const int kadd    = ((lane >> 4) & 1) * 8;
    const uint32_t lmoff = (uint32_t)(row_off * (ASTR * 2) + kadd * 2);

    const uint32_t sKh_b = smem_u32(sKh), sKl_b = smem_u32(sKl);
    const uint32_t sVh_b = smem_u32(sVh), sVl_b = smem_u32(sVl);

    #pragma unroll
    for (int i = 0; i < 4; i++) {
        int idx = tid + i * 128;
        int r = idx >> 3, c8 = idx & 7;
        uint32_t so = (uint32_t)(r * (ASTR * 2) + c8 * 16);
        size_t gi = baseqk + (size_t)(qt * 64 + r) * HD + c8 * 8;
        *(uint4*)((char*)sKh + so) = *(const uint4*)&g_Qhi[gi];
        *(uint4*)((char*)sKl + so) = *(const uint4*)&g_Qlo[gi];
    }
    __syncthreads();
    uint32_t qh[4][4], ql[4][4];
    #pragma unroll
    for (int kc = 0; kc < 4; kc++) {
        uint32_t aoff = (uint32_t)((wid * 16) * (ASTR * 2) + kc * 32) + lmoff;
        ldsm_x4(qh[kc], sKh_b + aoff);
        ldsm_x4(ql[kc], sKl_b + aoff);
    }
    __syncthreads();

    float o[8][4];
    #pragma unroll
    for (int nt = 0; nt < 8; nt++)
        #pragma unroll
        for (int q = 0; q < 4; q++) o[nt][q] = 0.0f;
    float m0 = -1e30f, m1 = -1e30f, l0 = 0.0f, l1 = 0.0f;

    const int qg0 = qt * 64 + wid * 16 + (lane >> 2);

    for (int kt = 0; kt <= qt; kt++) {
        #pragma unroll
        for (int i = 0; i < 4; i++) {
            int idx = tid + i * 128;
            int r = idx >> 3, c8 = idx & 7;
            uint32_t so = (uint32_t)(r * (ASTR * 2) + c8 * 16);
            size_t gk = baseqk + (size_t)(kt * 64 + r) * HD + c8 * 8;
            size_t gv = basev + (size_t)r * SS + kt * 64 + c8 * 8;
            *(uint4*)((char*)sKh + so) = *(const uint4*)&g_Khi[gk];
            *(uint4*)((char*)sKl + so) = *(const uint4*)&g_Klo[gk];
            *(uint4*)((char*)sVh + so) = *(const uint4*)&g_Vthi[gv];
            *(uint4*)((char*)sVl + so) = *(const uint4*)&g_Vtlo[gv];
        }
        if (tid < 64) {
            float mv = mask[b * SS + kt * 64 + tid];
            madd[tid] = (1.0f - mv) * NEG_INF;
        }
        __syncthreads();

        float s[8][4];
        #pragma unroll
        for (int nt = 0; nt < 8; nt++)
            #pragma unroll
            for (int q = 0; q < 4; q++) s[nt][q] = 0.0f;

        #pragma unroll
        for (int kc = 0; kc < 4; kc++) {
            uint32_t kh[4][4], kl[4][4];
            #pragma unroll
            for (int np = 0; np < 4; np++) {
                uint32_t boff = (uint32_t)((np * 16) * (ASTR * 2) + kc * 32) + lmoff;
                ldsm_x4(kh[np], sKh_b + boff);
                ldsm_x4(kl[np], sKl_b + boff);
            }
            #pragma unroll
            for (int nt = 0; nt < 8; nt++) {
                int np = nt >> 1, od = nt & 1;
                mma_bf16(s[nt], qh[kc], kh[np][od], kh[np][od + 2]);
                mma_bf16(s[nt], qh[kc], kl[np][od], kl[np][od + 2]);
                mma_bf16(s[nt], ql[kc], kh[np][od], kh[np][od + 2]);
            }
        }

        const bool diag = (kt == qt);
        #pragma unroll
        for (int nt = 0; nt < 8; nt++) {
            int c0 = nt * 8 + (lane & 3) * 2;
            float ma0 = madd[c0], ma1 = madd[c0 + 1];
            s[nt][0] += ma0; s[nt][1] += ma1;
            s[nt][2] += ma0; s[nt][3] += ma1;
            if (diag) {
                int kg = kt * 64 + c0;
                if (kg     > qg0)     s[nt][0] = NEG_INF;
                if (kg + 1 > qg0)     s[nt][1] = NEG_INF;
                if (kg     > qg0 + 8) s[nt][2] = NEG_INF;
                if (kg + 1 > qg0 + 8) s[nt][3] = NEG_INF;
            }
        }
        float mx0 = -1e30f, mx1 = -1e30f;
        #pragma unroll
        for (int nt = 0; nt < 8; nt++) {
            mx0 = fmaxf(mx0, fmaxf(s[nt][0], s[nt][1]));
            mx1 = fmaxf(mx1, fmaxf(s[nt][2], s[nt][3]));
        }
        mx0 = fmaxf(mx0, __shfl_xor_sync(0xffffffffu, mx0, 1));
        mx0 = fmaxf(mx0, __shfl_xor_sync(0xffffffffu, mx0, 2));
        mx1 = fmaxf(mx1, __shfl_xor_sync(0xffffffffu, mx1, 1));
        mx1 = fmaxf(mx1, __shfl_xor_sync(0xffffffffu, mx1, 2));
        float mn0 = fmaxf(m0, mx0), mn1 = fmaxf(m1, mx1);
        float a0 = __expf(m0 - mn0), a1 = __expf(m1 - mn1);
        m0 = mn0; m1 = mn1;

        float ps0 = 0.0f, ps1 = 0.0f;
        #pragma unroll
        for (int nt = 0; nt < 8; nt++) {
            s[nt][0] = __expf(s[nt][0] - mn0);
            s[nt][1] = __expf(s[nt][1] - mn0);
            s[nt][2] = __expf(s[nt][2] - mn1);
            s[nt][3] = __expf(s[nt][3] - mn1);
            ps0 += s[nt][0] + s[nt][1];
            ps1 += s[nt][2] + s[nt][3];
        }
        ps0 += __shfl_xor_sync(0xffffffffu, ps0, 1);
        ps0 += __shfl_xor_sync(0xffffffffu, ps0, 2);
        ps1 += __shfl_xor_sync(0xffffffffu, ps1, 1);
        ps1 += __shfl_xor_sync(0xffffffffu, ps1, 2);
        l0 = l0 * a0 + ps0;
        l1 = l1 * a1 + ps1;
        #pragma unroll
        for (int nt = 0; nt < 8; nt++) {
            o[nt][0] *= a0; o[nt][1] *= a0;
            o[nt][2] *= a1; o[nt][3] *= a1;
        }

        #pragma unroll
        for (int t = 0; t < 4; t++) {
            __nv_bfloat16 h0 = __float2bfloat16(s[2*t][0]);
            __nv_bfloat16 h1 = __float2bfloat16(s[2*t][1]);
            __nv_bfloat16 h2 = __float2bfloat16(s[2*t][2]);
            __nv_bfloat16 h3 = __float2bfloat16(s[2*t][3]);
            __nv_bfloat16 h4 = __float2bfloat16(s[2*t+1][0]);
            __nv_bfloat16 h5 = __float2bfloat16(s[2*t+1][1]);
            __nv_bfloat16 h6 = __float2bfloat16(s[2*t+1][2]);
            __nv_bfloat16 h7 = __float2bfloat16(s[2*t+1][3]);
            uint32_t ph[4], pl[4];
            ph[0] = packh(h0, h1);
            ph[1] = packh(h2, h3);
            ph[2] = packh(h4, h5);
            ph[3] = packh(h6, h7);
            pl[0] = packh(__float2bfloat16(s[2*t][0]   - __bfloat162float(h0)),
                          __float2bfloat16(s[2*t][1]   - __bfloat162float(h1)));
            pl[1] = packh(__float2bfloat16(s[2*t][2]   - __bfloat162float(h2)),
                          __float2bfloat16(s[2*t][3]   - __bfloat162float(h3)));
            pl[2] = packh(__float2bfloat16(s[2*t+1][0] - __bfloat162float(h4)),
                          __float2bfloat16(s[2*t+1][1] - __bfloat162float(h5)));
            pl[3] = packh(__float2bfloat16(s[2*t+1][2] - __bfloat162float(h6)),
                          __float2bfloat16(s[2*t+1][3] - __bfloat162float(h7)));

            uint32_t vh[4][4], vl[4][4];
            #pragma unroll
            for (int np = 0; np < 4; np++) {
                uint32_t voff = (uint32_t)((np * 16) * (ASTR * 2) + t * 32) + lmoff;
                ldsm_x4(vh[np], sVh_b + voff);
                ldsm_x4(vl[np], sVl_b + voff);
            }
            #pragma unroll
            for (int nt = 0; nt < 8; nt++) {
                int np = nt >> 1, od = nt & 1;
                mma_bf16(o[nt], ph, vh[np][od], vh[np][od + 2]);
                mma_bf16(o[nt], ph, vl[np][od], vl[np][od + 2]);
                mma_bf16(o[nt], pl, vh[np][od], vh[np][od + 2]);
            }
        }
        __syncthreads();
    }

    // ---- finalize + write split bf16 directly to g_xhi/g_xlo [B,S,Dm] ----
    float il0 = 1.0f / l0, il1 = 1.0f / l1;
    const int row = qt * 64 + wid * 16 + (lane >> 2);
    #pragma unroll
    for (int nt = 0; nt < 8; nt++) {
        int col = h * HD + nt * 8 + (lane & 3) * 2;
        size_t i0 = ((size_t)(b * SS) + row) * DM + col;
        size_t i1 = ((size_t)(b * SS) + row + 8) * DM + col;
        float v0 = o[nt][0] * il0, v1 = o[nt][1] * il0;
        float v2 = o[nt][2] * il1, v3 = o[nt][3] * il1;
        __nv_bfloat16 hh0 = __float2bfloat16(v0);
        __nv_bfloat16 hh1 = __float2bfloat16(v1);
        __nv_bfloat16 hh2 = __float2bfloat16(v2);
        __nv_bfloat16 hh3 = __float2bfloat16(v3);
        *(__nv_bfloat162*)&g_xhi[i0] = __nv_bfloat162(hh0, hh1);
        *(__nv_bfloat162*)&g_xhi[i1] = __nv_bfloat162(hh2, hh3);
        *(__nv_bfloat162*)&g_xlo[i0] =
            __nv_bfloat162(__float2bfloat16(v0 - __bfloat162float(hh0)),
                           __float2bfloat16(v1 - __bfloat162float(hh1)));
        *(__nv_bfloat162*)&g_xlo[i1] =
            __nv_bfloat162(__float2bfloat16(v2 - __bfloat162float(hh2)),
                           __float2bfloat16(v3 - __bfloat162float(hh3)));
    }
}

// ---------------------------------------------------------------------------
extern "C" void kernel_launch(void* const* d_in, const int* in_sizes, int n_in,
                              void* d_out, int out_size)
{
    const float* x    = (const float*)d_in[0];
    const float* mask = (const float*)d_in[1];
    const float* Wq   = (const float*)d_in[2];
    const float* Wk   = (const float*)d_in[3];
    const float* Wv   = (const float*)d_in[4];
    const float* Wo   = (const float*)d_in[5];
    float* out = (float*)d_out;

    float *tq, *tk, *tv;
    __nv_bfloat16 *xhi, *xlo, *wthi, *wtlo;
    cudaGetSymbolAddress((void**)&tq, g_tq);
    cudaGetSymbolAddress((void**)&tk, g_tk);
    cudaGetSymbolAddress((void**)&tv, g_tv);
    cudaGetSymbolAddress((void**)&xhi, g_xhi);
    cudaGetSymbolAddress((void**)&xlo, g_xlo);
    cudaGetSymbolAddress((void**)&wthi, g_wthi);
    cudaGetSymbolAddress((void**)&wtlo, g_wtlo);

    cudaFuncSetAttribute(gemm_tc_kernel,
                         cudaFuncAttributeMaxDynamicSharedMemorySize, GSM_TOTAL);

    const int M = BB * SS;   // 4096
    const int NELEM = BB * SS * DM;

    // 0) prep: input split, weight transpose+split, trig table
    split_kernel<<<NELEM / 1024, 256>>>(x, xhi, xlo);
    wsplit_kernel<<<dim3(DM / 32, DM / 32, 4), 256>>>(Wq, Wk, Wv, Wo);
    trig_kernel<<<(SS * 32) / 256, 256>>>();

    // 1) fused QKV projections (HMMA split-bf16, 512 thr, cp.async pipeline)
    gemm_tc_kernel<<<dim3(DM / GBN, M / GBM, 3), 512, GSM_TOTAL>>>(
        xhi, xlo, wthi, wtlo, tq, tk, tv);

    // 2) RoPE (table-based) + transpose + split for Q,K; V transpose + split
    ropeqk_kernel<<<dim3((BB * NH * SS * 32) / 256, 2), 256>>>();
    vtrans_kernel<<<dim3(SS / 32, NH, BB), 256>>>();

    // 3) causal flash attention (HMMA split-bf16), writes split output
    attention_tc_kernel<<<dim3(SS / 64, BB * NH), 128>>>(mask);

    // 4) O projection (reads split written by attention)
    gemm_tc_kernel<<<dim3(DM / GBN, M / GBM, 1), 512, GSM_TOTAL>>>(
        xhi, xlo, wthi + 3 * (size_t)DM * DM, wtlo + 3 * (size_t)DM * DM,
        out, out, out);
}

// round 7
// speedup vs baseline: 1.0428x; 1.0428x over previous
#include <cuda_runtime.h>
#include <cuda_bf16.h>
#include <math.h>
#include <stdint.h>

#define BB 2
#define SS 2048
#define DM 1024
#define NH 16
#define HD 64
#define NEG_INF -1000000000.0f

// ---------------- scratch (device globals: allocation-free) ----------------
__device__ float g_tq[BB*SS*DM];   // x@Wq  [B,S,Dm]
__device__ float g_tk[BB*SS*DM];
__device__ float g_tv[BB*SS*DM];

__device__ __nv_bfloat16 g_xhi[BB*SS*DM];       // activation split
__device__ __nv_bfloat16 g_xlo[BB*SS*DM];
__device__ __nv_bfloat16 g_wthi[4*DM*DM];       // W^T split: [z][N][K]
__device__ __nv_bfloat16 g_wtlo[4*DM*DM];

__device__ __nv_bfloat16 g_Qhi[BB*NH*SS*HD];    // [B,H,S,Hd], pre-scaled
__device__ __nv_bfloat16 g_Qlo[BB*NH*SS*HD];
__device__ __nv_bfloat16 g_Khi[BB*NH*SS*HD];
__device__ __nv_bfloat16 g_Klo[BB*NH*SS*HD];
__device__ __nv_bfloat16 g_Vthi[BB*NH*HD*SS];   // [B,H,Hd,S] (transposed)
__device__ __nv_bfloat16 g_Vtlo[BB*NH*HD*SS];

__device__ float g_cos[SS*32];
__device__ float g_sin[SS*32];

// ================= warp-MMA helpers (sm_103 base, no 'a' features) ==========
__device__ __forceinline__ uint32_t smem_u32(const void* p) {
    uint32_t a;
    asm("{ .reg .u64 t; cvta.to.shared.u64 t, %1; cvt.u32.u64 %0, t; }" : "=r"(a) : "l"(p));
    return a;
}
__device__ __forceinline__ void ldsm_x4(uint32_t* r, uint32_t addr) {
    asm volatile("ldmatrix.sync.aligned.m8n8.x4.shared.b16 {%0,%1,%2,%3}, [%4];"
                 : "=r"(r[0]), "=r"(r[1]), "=r"(r[2]), "=r"(r[3]) : "r"(addr));
}
__device__ __forceinline__ void mma_bf16(float* c, const uint32_t* a,
                                         uint32_t b0, uint32_t b1) {
    asm volatile(
        "mma.sync.aligned.m16n8k16.row.col.f32.bf16.bf16.f32 "
        "{%0,%1,%2,%3}, {%4,%5,%6,%7}, {%8,%9}, {%0,%1,%2,%3};"
        : "+f"(c[0]), "+f"(c[1]), "+f"(c[2]), "+f"(c[3])
        : "r"(a[0]), "r"(a[1]), "r"(a[2]), "r"(a[3]), "r"(b0), "r"(b1));
}
__device__ __forceinline__ uint32_t packh(__nv_bfloat16 a, __nv_bfloat16 b) {
    return ((uint32_t)__bfloat16_as_ushort(b) << 16) | (uint32_t)__bfloat16_as_ushort(a);
}
__device__ __forceinline__ void cp_async16(uint32_t saddr, const void* gaddr) {
    asm volatile("cp.async.cg.shared.global [%0], [%1], 16;"
                 :: "r"(saddr), "l"(gaddr) : "memory");
}
__device__ __forceinline__ void cp_commit() {
    asm volatile("cp.async.commit_group;" ::: "memory");
}
template<int N> __device__ __forceinline__ void cp_wait() {
    asm volatile("cp.async.wait_group %0;" :: "n"(N) : "memory");
}

// ================= split / weight-prep kernels ==============================
__global__ __launch_bounds__(256)
void split_kernel(const float* __restrict__ src,
                  __nv_bfloat16* __restrict__ hi,
                  __nv_bfloat16* __restrict__ lo)
{
    int i = (blockIdx.x * 256 + threadIdx.x) * 4;
    float4 v = *(const float4*)&src[i];
    __nv_bfloat16 h0 = __float2bfloat16(v.x);
    __nv_bfloat16 h1 = __float2bfloat16(v.y);
    __nv_bfloat16 h2 = __float2bfloat16(v.z);
    __nv_bfloat16 h3 = __float2bfloat16(v.w);
    __nv_bfloat16 l0 = __float2bfloat16(v.x - __bfloat162float(h0));
    __nv_bfloat16 l1 = __float2bfloat16(v.y - __bfloat162float(h1));
    __nv_bfloat16 l2 = __float2bfloat16(v.z - __bfloat162float(h2));
    __nv_bfloat16 l3 = __float2bfloat16(v.w - __bfloat162float(h3));
    *(__nv_bfloat162*)&hi[i]     = __nv_bfloat162(h0, h1);
    *(__nv_bfloat162*)&hi[i + 2] = __nv_bfloat162(h2, h3);
    *(__nv_bfloat162*)&lo[i]     = __nv_bfloat162(l0, l1);
    *(__nv_bfloat162*)&lo[i + 2] = __nv_bfloat162(l2, l3);
}

__global__ __launch_bounds__(256)
void wsplit_kernel(const float* __restrict__ Wq, const float* __restrict__ Wk,
                   const float* __restrict__ Wv, const float* __restrict__ Wo)
{
    __shared__ float tile[32][33];
    int z = blockIdx.z;
    const float* __restrict__ W = (z == 0) ? Wq : ((z == 1) ? Wk : ((z == 2) ? Wv : Wo));
    int n0 = blockIdx.x * 32;
    int k0 = blockIdx.y * 32;
    int tx = threadIdx.x & 31;
    int ty = threadIdx.x >> 5;
    #pragma unroll
    for (int i = 0; i < 4; i++) {
        int k = ty + i * 8;
        tile[k][tx] = W[(size_t)(k0 + k) * DM + n0 + tx];
    }
    __syncthreads();
    #pragma unroll
    for (int i = 0; i < 4; i++) {
        int n = ty + i * 8;
        float v = tile[tx][n];
        __nv_bfloat16 h = __float2bfloat16(v);
        __nv_bfloat16 l = __float2bfloat16(v - __bfloat162float(h));
        size_t di = ((size_t)z * DM + n0 + n) * DM + k0 + tx;
        g_wthi[di] = h;
        g_wtlo[di] = l;
    }
}

// ================= HMMA split-bf16 GEMM (2-stage cp.async, term-major) ======
#define GBM 128
#define GBN 128
#define GBK 32
#define GSTR 40
#define STB (GBM * GSTR * 2)          // bytes per array per stage = 10240
#define GSM_TOTAL (8 * STB)           // 2 stages x 4 arrays = 81920

__global__ __launch_bounds__(256)
void gemm_tc_kernel(const __nv_bfloat16* __restrict__ Ahi,
                    const __nv_bfloat16* __restrict__ Alo,
                    const __nv_bfloat16* __restrict__ Whi,
                    const __nv_bfloat16* __restrict__ Wlo,
                    float* __restrict__ C0, float* __restrict__ C1,
                    float* __restrict__ C2)
{
    extern __shared__ __align__(16) char dsm[];

    const int tid  = threadIdx.x;
    const int wid  = tid >> 5;
    const int lane = tid & 31;
    const int m0 = blockIdx.y * GBM;
    const int n0 = blockIdx.x * GBN;
    const int z  = blockIdx.z;
    const __nv_bfloat16* __restrict__ Wh = Whi + (size_t)z * DM * DM;
    const __nv_bfloat16* __restrict__ Wl = Wlo + (size_t)z * DM * DM;
    float* __restrict__ C = (z == 0) ? C0 : ((z == 1) ? C1 : C2);

    const int wm = wid & 1;
    const int wn = wid >> 1;

    const int row_off = (lane & 7) + ((lane >> 3) & 1) * 8;
    const int kadd    = ((lane >> 4) & 1) * 8;
    const uint32_t lmoff = (uint32_t)(row_off * (GSTR * 2) + kadd * 2);

    const uint32_t sbase = smem_u32(dsm);
    const int r_a = tid >> 2;
    const int c_a = tid & 3;
    const uint32_t so0 = (uint32_t)(r_a * (GSTR * 2) + c_a * 16);
    const uint32_t so1 = (uint32_t)((r_a + 64) * (GSTR * 2) + c_a * 16);

    float acc[4][4][4];
    #pragma unroll
    for (int i = 0; i < 4; i++)
        #pragma unroll
        for (int j = 0; j < 4; j++)
            #pragma unroll
            for (int q = 0; q < 4; q++) acc[i][j][q] = 0.0f;

    const int NK = DM / GBK;   // 32

    {
        uint32_t s0 = sbase;
        size_t ga0 = (size_t)(m0 + r_a) * DM + c_a * 8;
        size_t ga1 = (size_t)(m0 + r_a + 64) * DM + c_a * 8;
        size_t gb0 = (size_t)(n0 + r_a) * DM + c_a * 8;
        size_t gb1 = (size_t)(n0 + r_a + 64) * DM + c_a * 8;
        cp_async16(s0 + so0,           &Ahi[ga0]);
        cp_async16(s0 + so1,           &Ahi[ga1]);
        cp_async16(s0 + STB + so0,     &Alo[ga0]);
        cp_async16(s0 + STB + so1,     &Alo[ga1]);
        cp_async16(s0 + 2*STB + so0,   &Wh[gb0]);
        cp_async16(s0 + 2*STB + so1,   &Wh[gb1]);
        cp_async16(s0 + 3*STB + so0,   &Wl[gb0]);
        cp_async16(s0 + 3*STB + so1,   &Wl[gb1]);
        cp_commit();
    }

    for (int kc = 0; kc < NK; kc++) {
        if (kc + 1 < NK) {
            const int k0 = (kc + 1) * GBK;
            uint32_t s0 = sbase + (uint32_t)(((kc + 1) & 1) * 4 * STB);
            size_t ga0 = (size_t)(m0 + r_a) * DM + k0 + c_a * 8;
            size_t ga1 = (size_t)(m0 + r_a + 64) * DM + k0 + c_a * 8;
            size_t gb0 = (size_t)(n0 + r_a) * DM + k0 + c_a * 8;
            size_t gb1 = (size_t)(n0 + r_a + 64) * DM + k0 + c_a * 8;
            cp_async16(s0 + so0,           &Ahi[ga0]);
            cp_async16(s0 + so1,           &Ahi[ga1]);
            cp_async16(s0 + STB + so0,     &Alo[ga0]);
            cp_async16(s0 + STB + so1,     &Alo[ga1]);
            cp_async16(s0 + 2*STB + so0,   &Wh[gb0]);
            cp_async16(s0 + 2*STB + so1,   &Wh[gb1]);
            cp_async16(s0 + 3*STB + so0,   &Wl[gb0]);
            cp_async16(s0 + 3*STB + so1,   &Wl[gb1]);
            cp_commit();
            cp_wait<1>();
        } else {
            cp_wait<0>();
        }
        __syncthreads();

        const uint32_t st = sbase + (uint32_t)((kc & 1) * 4 * STB);
        const uint32_t sAh_b = st;
        const uint32_t sAl_b = st + STB;
        const uint32_t sBh_b = st + 2 * STB;
        const uint32_t sBl_b = st + 3 * STB;

        #pragma unroll
        for (int ks = 0; ks < 2; ks++) {
            uint32_t ah[4][4], al[4][4];
            #pragma unroll
            for (int mt = 0; mt < 4; mt++) {
                uint32_t aoff = (uint32_t)((wm * 64 + mt * 16) * (GSTR * 2) + ks * 32) + lmoff;
                ldsm_x4(ah[mt], sAh_b + aoff);
                ldsm_x4(al[mt], sAl_b + aoff);
            }
            uint32_t bh[2][4], bl[2][4];
            #pragma unroll
            for (int nt2 = 0; nt2 < 2; nt2++) {
                uint32_t boff = (uint32_t)((wn * 32 + nt2 * 16) * (GSTR * 2) + ks * 32) + lmoff;
                ldsm_x4(bh[nt2], sBh_b + boff);
                ldsm_x4(bl[nt2], sBl_b + boff);
            }
            // term-major passes: dependent MMAs on the same acc are 16 apart
            #pragma unroll
            for (int mt = 0; mt < 4; mt++)
                #pragma unroll
                for (int nt = 0; nt < 4; nt++) {
                    int n2 = nt >> 1, od = nt & 1;
                    mma_bf16(acc[mt][nt], ah[mt], bh[n2][od], bh[n2][od + 2]);
                }
            #pragma unroll
            for (int mt = 0; mt < 4; mt++)
                #pragma unroll
                for (int nt = 0; nt < 4; nt++) {
                    int n2 = nt >> 1, od = nt & 1;
                    mma_bf16(acc[mt][nt], ah[mt], bl[n2][od], bl[n2][od + 2]);
                }
            #pragma unroll
            for (int mt = 0; mt < 4; mt++)
                #pragma unroll
                for (int nt = 0; nt < 4; nt++) {
                    int n2 = nt >> 1, od = nt & 1;
                    mma_bf16(acc[mt][nt], al[mt], bh[n2][od], bh[n2][od + 2]);
                }
        }
        __syncthreads();
    }

    const int g   = lane >> 2;
    const int tig = lane & 3;
    #pragma unroll
    for (int mt = 0; mt < 4; mt++) {
        int row = m0 + wm * 64 + mt * 16 + g;
        #pragma unroll
        for (int nt = 0; nt < 4; nt++) {
            int col = n0 + wn * 32 + nt * 8 + tig * 2;
            *(float2*)&C[(size_t)row * DM + col]       = make_float2(acc[mt][nt][0], acc[mt][nt][1]);
            *(float2*)&C[(size_t)(row + 8) * DM + col] = make_float2(acc[mt][nt][2], acc[mt][nt][3]);
        }
    }
}

// ---------------- trig table (double precision, tiny) ----------------------
__global__ __launch_bounds__(256)
void trig_kernel()
{
    int idx = blockIdx.x * 256 + threadIdx.x;   // [0, SS*32)
    int s = idx >> 5, j = idx & 31;
    double inv = exp(-(double)j * (9.210340371976184 / 32.0));
    double ang = (double)s * inv;
    double sn, cs;
    sincos(ang, &sn, &cs);
    g_cos[idx] = (float)cs;
    g_sin[idx] = (float)sn;
}

// ---------------- RoPE + transpose + split: Q, K ----------------------------
__global__ __launch_bounds__(256)
void ropeqk_kernel()
{
    const int which = blockIdx.y;   // 0 = Q, 1 = K
    const float* __restrict__ src = (which == 0) ? g_tq : g_tk;
    __nv_bfloat16* __restrict__ dhi = (which == 0) ? g_Qhi : g_Khi;
    __nv_bfloat16* __restrict__ dlo = (which == 0) ? g_Qlo : g_Klo;
    const float scale = (which == 0) ? 0.125f : 1.0f;

    int idx = blockIdx.x * 256 + threadIdx.x;
    int j = idx & 31;
    int s = (idx >> 5) & (SS - 1);
    int h = (idx >> 16) & (NH - 1);
    int b = idx >> 20;

    size_t si = ((size_t)(b * SS + s)) * DM + h * HD;
    float t1 = src[si + j];
    float t2 = src[si + 32 + j];
    float c  = g_cos[s * 32 + j];
    float sn = g_sin[s * 32 + j];
    float o1 = (t1 * c - t2 * sn) * scale;
    float o2 = (t1 * sn + t2 * c) * scale;

    __nv_bfloat16 h1 = __float2bfloat16(o1);
    __nv_bfloat16 h2 = __float2bfloat16(o2);
    __nv_bfloat16 l1 = __float2bfloat16(o1 - __bfloat162float(h1));
    __nv_bfloat16 l2 = __float2bfloat16(o2 - __bfloat162float(h2));

    size_t di = (((size_t)(b * NH + h)) * SS + s) * HD;
    dhi[di + j]      = h1;
    dhi[di + 32 + j] = h2;
    dlo[di + j]      = l1;
    dlo[di + 32 + j] = l2;
}

// ---------------- V transpose + split: [B,S,Dm] -> [B,H,Hd,S] ---------------
__global__ __launch_bounds__(256)
void vtrans_kernel()
{
    __shared__ float tile[32][65];
    const int st = blockIdx.x;
    const int h  = blockIdx.y;
    const int b  = blockIdx.z;
    const int tid = threadIdx.x;

    const float* __restrict__ src = g_tv + ((size_t)(b * SS + st * 32)) * DM + h * HD;
    #pragma unroll
    for (int i = 0; i < 8; i++) {
        int idx = tid + i * 256;
        int r = idx >> 6, c = idx & 63;
        tile[r][c] = src[(size_t)r * DM + c];
    }
    __syncthreads();
    #pragma unroll
    for (int i = 0; i < 8; i++) {
        int idx = tid + i * 256;
        int c = idx >> 5, r = idx & 31;
        float v = tile[r][c];
        __nv_bfloat16 hh = __float2bfloat16(v);
        __nv_bfloat16 ll = __float2bfloat16(v - __bfloat162float(hh));
        size_t di = ((size_t)(b * NH + h) * HD + c) * SS + st * 32 + r;
        g_Vthi[di] = hh;
        g_Vtlo[di] = ll;
    }
}

// ---------------- HMMA split-bf16 flash attention (term-major) --------------
#define ASTR 72

__global__ __launch_bounds__(128)
void attention_tc_kernel(const float* __restrict__ mask)
{
    __shared__ __align__(16) __nv_bfloat16 sKh[64 * ASTR];
    __shared__ __align__(16) __nv_bfloat16 sKl[64 * ASTR];
    __shared__ __align__(16) __nv_bfloat16 sVh[64 * ASTR];
    __shared__ __align__(16) __nv_bfloat16 sVl[64 * ASTR];
    __shared__ float madd[64];

    const int tid  = threadIdx.x;
    const int wid  = tid >> 5;
    const int lane = tid & 31;
    const int qt = gridDim.x - 1 - blockIdx.x;
    const int bh = blockIdx.y;
    const int b  = bh >> 4;
    const int h  = bh & 15;

    const size_t baseqk = (size_t)bh * SS * HD;
    const size_t basev  = (size_t)bh * HD * SS;

    const int row_off = (lane & 7) + ((lane >> 3) & 1) * 8;
    const int kadd    = ((lane >> 4) & 1) * 8;
    const uint32_t lmoff = (uint32_t)(row_off * (ASTR * 2) + kadd * 2);

    const uint32_t sKh_b = smem_u32(sKh), sKl_b = smem_u32(sKl);
    const uint32_t sVh_b = smem_u32(sVh), sVl_b = smem_u32(sVl);

    #pragma unroll
    for (int i = 0; i < 4; i++) {
        int idx = tid + i * 128;
        int r = idx >> 3, c8 = idx & 7;
        uint32_t so = (uint32_t)(r * (ASTR * 2) + c8 * 16);
        size_t gi = baseqk + (size_t)(qt * 64 + r) * HD + c8 * 8;
        *(uint4*)((char*)sKh + so) = *(const uint4*)&g_Qhi[gi];
        *(uint4*)((char*)sKl + so) = *(const uint4*)&g_Qlo[gi];
    }
    __syncthreads();
    uint32_t qh[4][4], ql[4][4];
    #pragma unroll
    for (int kc = 0; kc < 4; kc++) {
        uint32_t aoff = (uint32_t)((wid * 16) * (ASTR * 2) + kc * 32) + lmoff;
        ldsm_x4(qh[kc], sKh_b + aoff);
        ldsm_x4(ql[kc], sKl_b + aoff);
    }
    __syncthreads();

    float o[8][4];
    #pragma unroll
    for (int nt = 0; nt < 8; nt++)
        #pragma unroll
        for (int q = 0; q < 4; q++) o[nt][q] = 0.0f;
    float m0 = -1e30f, m1 = -1e30f, l0 = 0.0f, l1 = 0.0f;

    const int qg0 = qt * 64 + wid * 16 + (lane >> 2);

    for (int kt = 0; kt <= qt; kt++) {
        #pragma unroll
        for (int i = 0; i < 4; i++) {
            int idx = tid + i * 128;
            int r = idx >> 3, c8 = idx & 7;
            uint32_t so = (uint32_t)(r * (ASTR * 2) + c8 * 16);
            size_t gk = baseqk + (size_t)(kt * 64 + r) * HD + c8 * 8;
            size_t gv = basev + (size_t)r * SS + kt * 64 + c8 * 8;
            *(uint4*)((char*)sKh + so) = *(const uint4*)&g_Khi[gk];
            *(uint4*)((char*)sKl + so) = *(const uint4*)&g_Klo[gk];
            *(uint4*)((char*)sVh + so) = *(const uint4*)&g_Vthi[gv];
            *(uint4*)((char*)sVl + so) = *(const uint4*)&g_Vtlo[gv];
        }
        if (tid < 64) {
            float mv = mask[b * SS + kt * 64 + tid];
            madd[tid] = (1.0f - mv) * NEG_INF;
        }
        __syncthreads();

        float s[8][4];
        #pragma unroll
        for (int nt = 0; nt < 8; nt++)
            #pragma unroll
            for (int q = 0; q < 4; q++) s[nt][q] = 0.0f;

        #pragma unroll
        for (int kc = 0; kc < 4; kc++) {
            uint32_t kh[4][4], kl[4][4];
            #pragma unroll
            for (int np = 0; np < 4; np++) {
                uint32_t boff = (uint32_t)((np * 16) * (ASTR * 2) + kc * 32) + lmoff;
                ldsm_x4(kh[np], sKh_b + boff);
                ldsm_x4(kl[np], sKl_b + boff);
            }
            // term-major: dependents 8 apart
            #pragma unroll
            for (int nt = 0; nt < 8; nt++) {
                int np = nt >> 1, od = nt & 1;
                mma_bf16(s[nt], qh[kc], kh[np][od], kh[np][od + 2]);
            }
            #pragma unroll
            for (int nt = 0; nt < 8; nt++) {
                int np = nt >> 1, od = nt & 1;
                mma_bf16(s[nt], qh[kc], kl[np][od], kl[np][od + 2]);
            }
            #pragma unroll
            for (int nt = 0; nt < 8; nt++) {
                int np = nt >> 1, od = nt & 1;
                mma_bf16(s[nt], ql[kc], kh[np][od], kh[np][od + 2]);
            }
        }

        const bool diag = (kt == qt);
        #pragma unroll
        for (int nt = 0; nt < 8; nt++) {
            int c0 = nt * 8 + (lane & 3) * 2;
            float ma0 = madd[c0], ma1 = madd[c0 + 1];
            s[nt][0] += ma0; s[nt][1] += ma1;
            s[nt][2] += ma0; s[nt][3] += ma1;
            if (diag) {
                int kg = kt * 64 + c0;
                if (kg     > qg0)     s[nt][0] = NEG_INF;
                if (kg + 1 > qg0)     s[nt][1] = NEG_INF;
                if (kg     > qg0 + 8) s[nt][2] = NEG_INF;
                if (kg + 1 > qg0 + 8) s[nt][3] = NEG_INF;
            }
        }
        float mx0 = -1e30f, mx1 = -1e30f;
        #pragma unroll
        for (int nt = 0; nt < 8; nt++) {
            mx0 = fmaxf(mx0, fmaxf(s[nt][0], s[nt][1]));
            mx1 = fmaxf(mx1, fmaxf(s[nt][2], s[nt][3]));
        }
        mx0 = fmaxf(mx0, __shfl_xor_sync(0xffffffffu, mx0, 1));
        mx0 = fmaxf(mx0, __shfl_xor_sync(0xffffffffu, mx0, 2));
        mx1 = fmaxf(mx1, __shfl_xor_sync(0xffffffffu, mx1, 1));
        mx1 = fmaxf(mx1, __shfl_xor_sync(0xffffffffu, mx1, 2));
        float mn0 = fmaxf(m0, mx0), mn1 = fmaxf(m1, mx1);
        float a0 = __expf(m0 - mn0), a1 = __expf(m1 - mn1);
        m0 = mn0; m1 = mn1;

        float ps0 = 0.0f, ps1 = 0.0f;
        #pragma unroll
        for (int nt = 0; nt < 8; nt++) {
            s[nt][0] = __expf(s[nt][0] - mn0);
            s[nt][1] = __expf(s[nt][1] - mn0);
            s[nt][2] = __expf(s[nt][2] - mn1);
            s[nt][3] = __expf(s[nt][3] - mn1);
            ps0 += s[nt][0] + s[nt][1];
            ps1 += s[nt][2] + s[nt][3];
        }
        ps0 += __shfl_xor_sync(0xffffffffu, ps0, 1);
        ps0 += __shfl_xor_sync(0xffffffffu, ps0, 2);
        ps1 += __shfl_xor_sync(0xffffffffu, ps1, 1);
        ps1 += __shfl_xor_sync(0xffffffffu, ps1, 2);
        l0 = l0 * a0 + ps0;
        l1 = l1 * a1 + ps1;
        #pragma unroll
        for (int nt = 0; nt < 8; nt++) {
            o[nt][0] *= a0; o[nt][1] *= a0;
            o[nt][2] *= a1; o[nt][3] *= a1;
        }

        #pragma unroll
        for (int t = 0; t < 4; t++) {
            __nv_bfloat16 h0 = __float2bfloat16(s[2*t][0]);
            __nv_bfloat16 h1 = __float2bfloat16(s[2*t][1]);
            __nv_bfloat16 h2 = __float2bfloat16(s[2*t][2]);
            __nv_bfloat16 h3 = __float2bfloat16(s[2*t][3]);
            __nv_bfloat16 h4 = __float2bfloat16(s[2*t+1][0]);
            __nv_bfloat16 h5 = __float2bfloat16(s[2*t+1][1]);
            __nv_bfloat16 h6 = __float2bfloat16(s[2*t+1][2]);
            __nv_bfloat16 h7 = __float2bfloat16(s[2*t+1][3]);
            uint32_t ph[4], pl[4];
            ph[0] = packh(h0, h1);
            ph[1] = packh(h2, h3);
            ph[2] = packh(h4, h5);
            ph[3] = packh(h6, h7);
            pl[0] = packh(__float2bfloat16(s[2*t][0]   - __bfloat162float(h0)),
                          __float2bfloat16(s[2*t][1]   - __bfloat162float(h1)));
            pl[1] = packh(__float2bfloat16(s[2*t][2]   - __bfloat162float(h2)),
                          __float2bfloat16(s[2*t][3]   - __bfloat162float(h3)));
            pl[2] = packh(__float2bfloat16(s[2*t+1][0] - __bfloat162float(h4)),
                          __float2bfloat16(s[2*t+1][1] - __bfloat162float(h5)));
            pl[3] = packh(__float2bfloat16(s[2*t+1][2] - __bfloat162float(h6)),
                          __float2bfloat16(s[2*t+1][3] - __bfloat162float(h7)));

            uint32_t vh[4][4], vl[4][4];
            #pragma unroll
            for (int np = 0; np < 4; np++) {
                uint32_t voff = (uint32_t)((np * 16) * (ASTR * 2) + t * 32) + lmoff;
                ldsm_x4(vh[np], sVh_b + voff);
                ldsm_x4(vl[np], sVl_b + voff);
            }
            // term-major: dependents 8 apart
            #pragma unroll
            for (int nt = 0; nt < 8; nt++) {
                int np = nt >> 1, od = nt & 1;
                mma_bf16(o[nt], ph, vh[np][od], vh[np][od + 2]);
            }
            #pragma unroll
            for (int nt = 0; nt < 8; nt++) {
                int np = nt >> 1, od = nt & 1;
                mma_bf16(o[nt], ph, vl[np][od], vl[np][od + 2]);
            }
            #pragma unroll
            for (int nt = 0; nt < 8; nt++) {
                int np = nt >> 1, od = nt & 1;
                mma_bf16(o[nt], pl, vh[np][od], vh[np][od + 2]);
            }
        }
        __syncthreads();
    }

    // ---- finalize + write split bf16 directly to g_xhi/g_xlo [B,S,Dm] ----
    float il0 = 1.0f / l0, il1 = 1.0f / l1;
    const int row = qt * 64 + wid * 16 + (lane >> 2);
    #pragma unroll
    for (int nt = 0; nt < 8; nt++) {
        int col = h * HD + nt * 8 + (lane & 3) * 2;
        size_t i0 = ((size_t)(b * SS) + row) * DM + col;
        size_t i1 = ((size_t)(b * SS) + row + 8) * DM + col;
        float v0 = o[nt][0] * il0, v1 = o[nt][1] * il0;
        float v2 = o[nt][2] * il1, v3 = o[nt][3] * il1;
        __nv_bfloat16 hh0 = __float2bfloat16(v0);
        __nv_bfloat16 hh1 = __float2bfloat16(v1);
        __nv_bfloat16 hh2 = __float2bfloat16(v2);
        __nv_bfloat16 hh3 = __float2bfloat16(v3);
        *(__nv_bfloat162*)&g_xhi[i0] = __nv_bfloat162(hh0, hh1);
        *(__nv_bfloat162*)&g_xhi[i1] = __nv_bfloat162(hh2, hh3);
        *(__nv_bfloat162*)&g_xlo[i0] =
            __nv_bfloat162(__float2bfloat16(v0 - __bfloat162float(hh0)),
                           __float2bfloat16(v1 - __bfloat162float(hh1)));
        *(__nv_bfloat162*)&g_xlo[i1] =
            __nv_bfloat162(__float2bfloat16(v2 - __bfloat162float(hh2)),
                           __float2bfloat16(v3 - __bfloat162float(hh3)));
    }
}

// ---------------------------------------------------------------------------
extern "C" void kernel_launch(void* const* d_in, const int* in_sizes, int n_in,
                              void* d_out, int out_size)
{
    const float* x    = (const float*)d_in[0];
    const float* mask = (const float*)d_in[1];
    const float* Wq   = (const float*)d_in[2];
    const float* Wk   = (const float*)d_in[3];
    const float* Wv   = (const float*)d_in[4];
    const float* Wo   = (const float*)d_in[5];
    float* out = (float*)d_out;

    float *tq, *tk, *tv;
    __nv_bfloat16 *xhi, *xlo, *wthi, *wtlo;
    cudaGetSymbolAddress((void**)&tq, g_tq);
    cudaGetSymbolAddress((void**)&tk, g_tk);
    cudaGetSymbolAddress((void**)&tv, g_tv);
    cudaGetSymbolAddress((void**)&xhi, g_xhi);
    cudaGetSymbolAddress((void**)&xlo, g_xlo);
    cudaGetSymbolAddress((void**)&wthi, g_wthi);
    cudaGetSymbolAddress((void**)&wtlo, g_wtlo);

    cudaFuncSetAttribute(gemm_tc_kernel,
                         cudaFuncAttributeMaxDynamicSharedMemorySize, GSM_TOTAL);

    const int M = BB * SS;   // 4096
    const int NELEM = BB * SS * DM;

    // 0) prep: input split, weight transpose+split, trig table
    split_kernel<<<NELEM / 1024, 256>>>(x, xhi, xlo);
    wsplit_kernel<<<dim3(DM / 32, DM / 32, 4), 256>>>(Wq, Wk, Wv, Wo);
    trig_kernel<<<(SS * 32) / 256, 256>>>();

    // 1) fused QKV projections (HMMA split-bf16, term-major, cp.async)
    gemm_tc_kernel<<<dim3(DM / GBN, M / GBM, 3), 256, GSM_TOTAL>>>(
        xhi, xlo, wthi, wtlo, tq, tk, tv);

    // 2) RoPE (table-based) + transpose + split for Q,K; V transpose + split
    ropeqk_kernel<<<dim3((BB * NH * SS * 32) / 256, 2), 256>>>();
    vtrans_kernel<<<dim3(SS / 32, NH, BB), 256>>>();

    // 3) causal flash attention (HMMA split-bf16, term-major)
    attention_tc_kernel<<<dim3(SS / 64, BB * NH), 128>>>(mask);

    // 4) O projection (reads split written by attention)
    gemm_tc_kernel<<<dim3(DM / GBN, M / GBM, 1), 256, GSM_TOTAL>>>(
        xhi, xlo, wthi + 3 * (size_t)DM * DM, wtlo + 3 * (size_t)DM * DM,
        out, out, out);
}

// round 8
// speedup vs baseline: 1.0680x; 1.0242x over previous
#include <cuda_runtime.h>
#include <cuda_bf16.h>
#include <math.h>
#include <stdint.h>

#define BB 2
#define SS 2048
#define DM 1024
#define NH 16
#define HD 64
#define NEG_INF -1000000000.0f

// ---------------- scratch (device globals: allocation-free) ----------------
__device__ float g_tq[BB*SS*DM];   // x@Wq  [B,S,Dm]
__device__ float g_tk[BB*SS*DM];
__device__ float g_tv[BB*SS*DM];

__device__ __nv_bfloat16 g_xhi[BB*SS*DM];       // activation split
__device__ __nv_bfloat16 g_xlo[BB*SS*DM];
__device__ __nv_bfloat16 g_wthi[4*DM*DM];       // W^T split: [z][N][K]
__device__ __nv_bfloat16 g_wtlo[4*DM*DM];

__device__ __nv_bfloat16 g_Qhi[BB*NH*SS*HD];    // [B,H,S,Hd], pre-scaled
__device__ __nv_bfloat16 g_Qlo[BB*NH*SS*HD];
__device__ __nv_bfloat16 g_Khi[BB*NH*SS*HD];
__device__ __nv_bfloat16 g_Klo[BB*NH*SS*HD];
__device__ __nv_bfloat16 g_Vthi[BB*NH*HD*SS];   // [B,H,Hd,S] (transposed)
__device__ __nv_bfloat16 g_Vtlo[BB*NH*HD*SS];

__device__ float g_cos[SS*32];
__device__ float g_sin[SS*32];

// ================= warp-MMA helpers (sm_103 base, no 'a' features) ==========
__device__ __forceinline__ uint32_t smem_u32(const void* p) {
    uint32_t a;
    asm("{ .reg .u64 t; cvta.to.shared.u64 t, %1; cvt.u32.u64 %0, t; }" : "=r"(a) : "l"(p));
    return a;
}
__device__ __forceinline__ void ldsm_x4(uint32_t* r, uint32_t addr) {
    asm volatile("ldmatrix.sync.aligned.m8n8.x4.shared.b16 {%0,%1,%2,%3}, [%4];"
                 : "=r"(r[0]), "=r"(r[1]), "=r"(r[2]), "=r"(r[3]) : "r"(addr));
}
__device__ __forceinline__ void mma_bf16(float* c, const uint32_t* a,
                                         uint32_t b0, uint32_t b1) {
    asm volatile(
        "mma.sync.aligned.m16n8k16.row.col.f32.bf16.bf16.f32 "
        "{%0,%1,%2,%3}, {%4,%5,%6,%7}, {%8,%9}, {%0,%1,%2,%3};"
        : "+f"(c[0]), "+f"(c[1]), "+f"(c[2]), "+f"(c[3])
        : "r"(a[0]), "r"(a[1]), "r"(a[2]), "r"(a[3]), "r"(b0), "r"(b1));
}
__device__ __forceinline__ uint32_t packh(__nv_bfloat16 a, __nv_bfloat16 b) {
    return ((uint32_t)__bfloat16_as_ushort(b) << 16) | (uint32_t)__bfloat16_as_ushort(a);
}
__device__ __forceinline__ void cp_async16(uint32_t saddr, const void* gaddr) {
    asm volatile("cp.async.cg.shared.global [%0], [%1], 16;"
                 :: "r"(saddr), "l"(gaddr) : "memory");
}
__device__ __forceinline__ void cp_commit() {
    asm volatile("cp.async.commit_group;" ::: "memory");
}
template<int N> __device__ __forceinline__ void cp_wait() {
    asm volatile("cp.async.wait_group %0;" :: "n"(N) : "memory");
}

// ================= split / weight-prep kernels ==============================
__global__ __launch_bounds__(256)
void split_kernel(const float* __restrict__ src,
                  __nv_bfloat16* __restrict__ hi,
                  __nv_bfloat16* __restrict__ lo)
{
    int i = (blockIdx.x * 256 + threadIdx.x) * 4;
    float4 v = *(const float4*)&src[i];
    __nv_bfloat16 h0 = __float2bfloat16(v.x);
    __nv_bfloat16 h1 = __float2bfloat16(v.y);
    __nv_bfloat16 h2 = __float2bfloat16(v.z);
    __nv_bfloat16 h3 = __float2bfloat16(v.w);
    __nv_bfloat16 l0 = __float2bfloat16(v.x - __bfloat162float(h0));
    __nv_bfloat16 l1 = __float2bfloat16(v.y - __bfloat162float(h1));
    __nv_bfloat16 l2 = __float2bfloat16(v.z - __bfloat162float(h2));
    __nv_bfloat16 l3 = __float2bfloat16(v.w - __bfloat162float(h3));
    *(__nv_bfloat162*)&hi[i]     = __nv_bfloat162(h0, h1);
    *(__nv_bfloat162*)&hi[i + 2] = __nv_bfloat162(h2, h3);
    *(__nv_bfloat162*)&lo[i]     = __nv_bfloat162(l0, l1);
    *(__nv_bfloat162*)&lo[i + 2] = __nv_bfloat162(l2, l3);
}

__global__ __launch_bounds__(256)
void wsplit_kernel(const float* __restrict__ Wq, const float* __restrict__ Wk,
                   const float* __restrict__ Wv, const float* __restrict__ Wo)
{
    __shared__ float tile[32][33];
    int z = blockIdx.z;
    const float* __restrict__ W = (z == 0) ? Wq : ((z == 1) ? Wk : ((z == 2) ? Wv : Wo));
    int n0 = blockIdx.x * 32;
    int k0 = blockIdx.y * 32;
    int tx = threadIdx.x & 31;
    int ty = threadIdx.x >> 5;
    #pragma unroll
    for (int i = 0; i < 4; i++) {
        int k = ty + i * 8;
        tile[k][tx] = W[(size_t)(k0 + k) * DM + n0 + tx];
    }
    __syncthreads();
    #pragma unroll
    for (int i = 0; i < 4; i++) {
        int n = ty + i * 8;
        float v = tile[tx][n];
        __nv_bfloat16 h = __float2bfloat16(v);
        __nv_bfloat16 l = __float2bfloat16(v - __bfloat162float(h));
        size_t di = ((size_t)z * DM + n0 + n) * DM + k0 + tx;
        g_wthi[di] = h;
        g_wtlo[di] = l;
    }
}

// ================= HMMA split-bf16 GEMM (4-stage cp.async, frag dbuf) =======
#define GBM 128
#define GBN 128
#define GBK 32
#define GSTR 40
#define STB (GBM * GSTR * 2)          // bytes per array = 10240
#define STAGE_B (4 * STB)             // 40960 per stage
#define GSTAGES 4
#define GSM_TOTAL (GSTAGES * STAGE_B) // 163840

// load one warp's fragments for a given ks half from stage base 'st'
__device__ __forceinline__ void load_frags(
    uint32_t ah[4][4], uint32_t al[4][4], uint32_t bh[2][4], uint32_t bl[2][4],
    uint32_t st, int ks, int wm, int wn, uint32_t lmoff)
{
    const uint32_t sAh = st, sAl = st + STB, sBh = st + 2 * STB, sBl = st + 3 * STB;
    #pragma unroll
    for (int mt = 0; mt < 4; mt++) {
        uint32_t aoff = (uint32_t)((wm * 64 + mt * 16) * (GSTR * 2) + ks * 32) + lmoff;
        ldsm_x4(ah[mt], sAh + aoff);
        ldsm_x4(al[mt], sAl + aoff);
    }
    #pragma unroll
    for (int nt2 = 0; nt2 < 2; nt2++) {
        uint32_t boff = (uint32_t)((wn * 32 + nt2 * 16) * (GSTR * 2) + ks * 32) + lmoff;
        ldsm_x4(bh[nt2], sBh + boff);
        ldsm_x4(bl[nt2], sBl + boff);
    }
}

// term-major MMA passes (order per accumulator: hh, hl, lh — numerics-stable)
__device__ __forceinline__ void mma_all(
    float acc[4][4][4],
    uint32_t ah[4][4], uint32_t al[4][4], uint32_t bh[2][4], uint32_t bl[2][4])
{
    #pragma unroll
    for (int mt = 0; mt < 4; mt++)
        #pragma unroll
        for (int nt = 0; nt < 4; nt++) {
            int n2 = nt >> 1, od = nt & 1;
            mma_bf16(acc[mt][nt], ah[mt], bh[n2][od], bh[n2][od + 2]);
        }
    #pragma unroll
    for (int mt = 0; mt < 4; mt++)
        #pragma unroll
        for (int nt = 0; nt < 4; nt++) {
            int n2 = nt >> 1, od = nt & 1;
            mma_bf16(acc[mt][nt], ah[mt], bl[n2][od], bl[n2][od + 2]);
        }
    #pragma unroll
    for (int mt = 0; mt < 4; mt++)
        #pragma unroll
        for (int nt = 0; nt < 4; nt++) {
            int n2 = nt >> 1, od = nt & 1;
            mma_bf16(acc[mt][nt], al[mt], bh[n2][od], bh[n2][od + 2]);
        }
}

__global__ __launch_bounds__(256)
void gemm_tc_kernel(const __nv_bfloat16* __restrict__ Ahi,
                    const __nv_bfloat16* __restrict__ Alo,
                    const __nv_bfloat16* __restrict__ Whi,
                    const __nv_bfloat16* __restrict__ Wlo,
                    float* __restrict__ C0, float* __restrict__ C1,
                    float* __restrict__ C2)
{
    extern __shared__ __align__(16) char dsm[];

    const int tid  = threadIdx.x;
    const int wid  = tid >> 5;
    const int lane = tid & 31;
    const int m0 = blockIdx.y * GBM;
    const int n0 = blockIdx.x * GBN;
    const int z  = blockIdx.z;
    const __nv_bfloat16* __restrict__ Wh = Whi + (size_t)z * DM * DM;
    const __nv_bfloat16* __restrict__ Wl = Wlo + (size_t)z * DM * DM;
    float* __restrict__ C = (z == 0) ? C0 : ((z == 1) ? C1 : C2);

    const int wm = wid & 1;
    const int wn = wid >> 1;

    const int row_off = (lane & 7) + ((lane >> 3) & 1) * 8;
    const int kadd    = ((lane >> 4) & 1) * 8;
    const uint32_t lmoff = (uint32_t)(row_off * (GSTR * 2) + kadd * 2);

    const uint32_t sbase = smem_u32(dsm);
    const int r_a = tid >> 2;
    const int c_a = tid & 3;
    const uint32_t so0 = (uint32_t)(r_a * (GSTR * 2) + c_a * 16);
    const uint32_t so1 = (uint32_t)((r_a + 64) * (GSTR * 2) + c_a * 16);

    float acc[4][4][4];
    #pragma unroll
    for (int i = 0; i < 4; i++)
        #pragma unroll
        for (int j = 0; j < 4; j++)
            #pragma unroll
            for (int q = 0; q < 4; q++) acc[i][j][q] = 0.0f;

    const int NK = DM / GBK;   // 32

    // cp.async issue for chunk kcc into its stage
    auto issue_cp = [&](int kcc) {
        const int k0 = kcc * GBK;
        uint32_t s0 = sbase + (uint32_t)((kcc % GSTAGES) * STAGE_B);
        size_t ga0 = (size_t)(m0 + r_a) * DM + k0 + c_a * 8;
        size_t ga1 = (size_t)(m0 + r_a + 64) * DM + k0 + c_a * 8;
        size_t gb0 = (size_t)(n0 + r_a) * DM + k0 + c_a * 8;
        size_t gb1 = (size_t)(n0 + r_a + 64) * DM + k0 + c_a * 8;
        cp_async16(s0 + so0,           &Ahi[ga0]);
        cp_async16(s0 + so1,           &Ahi[ga1]);
        cp_async16(s0 + STB + so0,     &Alo[ga0]);
        cp_async16(s0 + STB + so1,     &Alo[ga1]);
        cp_async16(s0 + 2*STB + so0,   &Wh[gb0]);
        cp_async16(s0 + 2*STB + so1,   &Wh[gb1]);
        cp_async16(s0 + 3*STB + so0,   &Wl[gb0]);
        cp_async16(s0 + 3*STB + so1,   &Wl[gb1]);
        cp_commit();
    };

    // bootstrap: stages 0..2 in flight; ensure g0,g1 landed
    issue_cp(0);
    issue_cp(1);
    issue_cp(2);
    cp_wait<1>();
    __syncthreads();

    uint32_t ahC[4][4], alC[4][4], bhC[2][4], blC[2][4];
    uint32_t ahN[4][4], alN[4][4], bhN[2][4], blN[2][4];

    // preload fragments (kc=0, ks=0)
    load_frags(ahC, alC, bhC, blC, sbase, 0, wm, wn, lmoff);

    for (int kc = 0; kc < NK; kc++) {
        const uint32_t stC = sbase + (uint32_t)((kc % GSTAGES) * STAGE_B);
        const uint32_t stN = sbase + (uint32_t)(((kc + 1) % GSTAGES) * STAGE_B);

        // prefetch (kc, ks1) while computing (kc, ks0)
        load_frags(ahN, alN, bhN, blN, stC, 1, wm, wn, lmoff);
        mma_all(acc, ahC, alC, bhC, blC);

        // prefetch (kc+1, ks0) while computing (kc, ks1)
        if (kc + 1 < NK)
            load_frags(ahC, alC, bhC, blC, stN, 0, wm, wn, lmoff);
        mma_all(acc, ahN, alN, bhN, blN);

        // feed the pipeline (after all reads of this region)
        if (kc + 3 < NK) {
            issue_cp(kc + 3);
            cp_wait<1>();
        } else {
            cp_wait<0>();
        }
        __syncthreads();
    }

    const int g   = lane >> 2;
    const int tig = lane & 3;
    #pragma unroll
    for (int mt = 0; mt < 4; mt++) {
        int row = m0 + wm * 64 + mt * 16 + g;
        #pragma unroll
        for (int nt = 0; nt < 4; nt++) {
            int col = n0 + wn * 32 + nt * 8 + tig * 2;
            *(float2*)&C[(size_t)row * DM + col]       = make_float2(acc[mt][nt][0], acc[mt][nt][1]);
            *(float2*)&C[(size_t)(row + 8) * DM + col] = make_float2(acc[mt][nt][2], acc[mt][nt][3]);
        }
    }
}

// ---------------- trig table (double precision, tiny) ----------------------
__global__ __launch_bounds__(256)
void trig_kernel()
{
    int idx = blockIdx.x * 256 + threadIdx.x;   // [0, SS*32)
    int s = idx >> 5, j = idx & 31;
    double inv = exp(-(double)j * (9.210340371976184 / 32.0));
    double ang = (double)s * inv;
    double sn, cs;
    sincos(ang, &sn, &cs);
    g_cos[idx] = (float)cs;
    g_sin[idx] = (float)sn;
}

// ---------------- RoPE + transpose + split: Q, K ----------------------------
__global__ __launch_bounds__(256)
void ropeqk_kernel()
{
    const int which = blockIdx.y;   // 0 = Q, 1 = K
    const float* __restrict__ src = (which == 0) ? g_tq : g_tk;
    __nv_bfloat16* __restrict__ dhi = (which == 0) ? g_Qhi : g_Khi;
    __nv_bfloat16* __restrict__ dlo = (which == 0) ? g_Qlo : g_Klo;
    const float scale = (which == 0) ? 0.125f : 1.0f;

    int idx = blockIdx.x * 256 + threadIdx.x;
    int j = idx & 31;
    int s = (idx >> 5) & (SS - 1);
    int h = (idx >> 16) & (NH - 1);
    int b = idx >> 20;

    size_t si = ((size_t)(b * SS + s)) * DM + h * HD;
    float t1 = src[si + j];
    float t2 = src[si + 32 + j];
    float c  = g_cos[s * 32 + j];
    float sn = g_sin[s * 32 + j];
    float o1 = (t1 * c - t2 * sn) * scale;
    float o2 = (t1 * sn + t2 * c) * scale;

    __nv_bfloat16 h1 = __float2bfloat16(o1);
    __nv_bfloat16 h2 = __float2bfloat16(o2);
    __nv_bfloat16 l1 = __float2bfloat16(o1 - __bfloat162float(h1));
    __nv_bfloat16 l2 = __float2bfloat16(o2 - __bfloat162float(h2));

    size_t di = (((size_t)(b * NH + h)) * SS + s) * HD;
    dhi[di + j]      = h1;
    dhi[di + 32 + j] = h2;
    dlo[di + j]      = l1;
    dlo[di + 32 + j] = l2;
}

// ---------------- V transpose + split: [B,S,Dm] -> [B,H,Hd,S] ---------------
__global__ __launch_bounds__(256)
void vtrans_kernel()
{
    __shared__ float tile[32][65];
    const int st = blockIdx.x;
    const int h  = blockIdx.y;
    const int b  = blockIdx.z;
    const int tid = threadIdx.x;

    const float* __restrict__ src = g_tv + ((size_t)(b * SS + st * 32)) * DM + h * HD;
    #pragma unroll
    for (int i = 0; i < 8; i++) {
        int idx = tid + i * 256;
        int r = idx >> 6, c = idx & 63;
        tile[r][c] = src[(size_t)r * DM + c];
    }
    __syncthreads();
    #pragma unroll
    for (int i = 0; i < 8; i++) {
        int idx = tid + i * 256;
        int c = idx >> 5, r = idx & 31;
        float v = tile[r][c];
        __nv_bfloat16 hh = __float2bfloat16(v);
        __nv_bfloat16 ll = __float2bfloat16(v - __bfloat162float(hh));
        size_t di = ((size_t)(b * NH + h) * HD + c) * SS + st * 32 + r;
        g_Vthi[di] = hh;
        g_Vtlo[di] = ll;
    }
}

// ---------------- HMMA split-bf16 flash attention (term-major) --------------
#define ASTR 72

__global__ __launch_bounds__(128)
void attention_tc_kernel(const float* __restrict__ mask)
{
    __shared__ __align__(16) __nv_bfloat16 sKh[64 * ASTR];
    __shared__ __align__(16) __nv_bfloat16 sKl[64 * ASTR];
    __shared__ __align__(16) __nv_bfloat16 sVh[64 * ASTR];
    __shared__ __align__(16) __nv_bfloat16 sVl[64 * ASTR];
    __shared__ float madd[64];

    const int tid  = threadIdx.x;
    const int wid  = tid >> 5;
    const int lane = tid & 31;
    const int qt = gridDim.x - 1 - blockIdx.x;
    const int bh = blockIdx.y;
    const int b  = bh >> 4;
    const int h  = bh & 15;

    const size_t baseqk = (size_t)bh * SS * HD;
    const size_t basev  = (size_t)bh * HD * SS;

    const int row_off = (lane & 7) + ((lane >> 3) & 1) * 8;
    const int kadd    = ((lane >> 4) & 1) * 8;
    const uint32_t lmoff = (uint32_t)(row_off * (ASTR * 2) + kadd * 2);

    const uint32_t sKh_b = smem_u32(sKh), sKl_b = smem_u32(sKl);
    const uint32_t sVh_b = smem_u32(sVh), sVl_b = smem_u32(sVl);

    #pragma unroll
    for (int i = 0; i < 4; i++) {
        int idx = tid + i * 128;
        int r = idx >> 3, c8 = idx & 7;
        uint32_t so = (uint32_t)(r * (ASTR * 2) + c8 * 16);
        size_t gi = baseqk + (size_t)(qt * 64 + r) * HD + c8 * 8;
        *(uint4*)((char*)sKh + so) = *(const uint4*)&g_Qhi[gi];
        *(uint4*)((char*)sKl + so) = *(const uint4*)&g_Qlo[gi];
    }
    __syncthreads();
    uint32_t qh[4][4], ql[4][4];
    #pragma unroll
    for (int kc = 0; kc < 4; kc++) {
        uint32_t aoff = (uint32_t)((wid * 16) * (ASTR * 2) + kc * 32) + lmoff;
        ldsm_x4(qh[kc], sKh_b + aoff);
        ldsm_x4(ql[kc], sKl_b + aoff);
    }
    __syncthreads();

    float o[8][4];
    #pragma unroll
    for (int nt = 0; nt < 8; nt++)
        #pragma unroll
        for (int q = 0; q < 4; q++) o[nt][q] = 0.0f;
    float m0 = -1e30f, m1 = -1e30f, l0 = 0.0f, l1 = 0.0f;

    const int qg0 = qt * 64 + wid * 16 + (lane >> 2);

    for (int kt = 0; kt <= qt; kt++) {
        #pragma unroll
        for (int i = 0; i < 4; i++) {
            int idx = tid + i * 128;
            int r = idx >> 3, c8 = idx & 7;
            uint32_t so = (uint32_t)(r * (ASTR * 2) + c8 * 16);
            size_t gk = baseqk + (size_t)(kt * 64 + r) * HD + c8 * 8;
            size_t gv = basev + (size_t)r * SS + kt * 64 + c8 * 8;
            *(uint4*)((char*)sKh + so) = *(const uint4*)&g_Khi[gk];
            *(uint4*)((char*)sKl + so) = *(const uint4*)&g_Klo[gk];
            *(uint4*)((char*)sVh + so) = *(const uint4*)&g_Vthi[gv];
            *(uint4*)((char*)sVl + so) = *(const uint4*)&g_Vtlo[gv];
        }
        if (tid < 64) {
            float mv = mask[b * SS + kt * 64 + tid];
            madd[tid] = (1.0f - mv) * NEG_INF;
        }
        __syncthreads();

        float s[8][4];
        #pragma unroll
        for (int nt = 0; nt < 8; nt++)
            #pragma unroll
            for (int q = 0; q < 4; q++) s[nt][q] = 0.0f;

        #pragma unroll
        for (int kc = 0; kc < 4; kc++) {
            uint32_t kh[4][4], kl[4][4];
            #pragma unroll
            for (int np = 0; np < 4; np++) {
                uint32_t boff = (uint32_t)((np * 16) * (ASTR * 2) + kc * 32) + lmoff;
                ldsm_x4(kh[np], sKh_b + boff);
                ldsm_x4(kl[np], sKl_b + boff);
            }
            #pragma unroll
            for (int nt = 0; nt < 8; nt++) {
                int np = nt >> 1, od = nt & 1;
                mma_bf16(s[nt], qh[kc], kh[np][od], kh[np][od + 2]);
            }
            #pragma unroll
            for (int nt = 0; nt < 8; nt++) {
                int np = nt >> 1, od = nt & 1;
                mma_bf16(s[nt], qh[kc], kl[np][od], kl[np][od + 2]);
            }
            #pragma unroll
            for (int nt = 0; nt < 8; nt++) {
                int np = nt >> 1, od = nt & 1;
                mma_bf16(s[nt], ql[kc], kh[np][od], kh[np][od + 2]);
            }
        }

        const bool diag = (kt == qt);
        #pragma unroll
        for (int nt = 0; nt < 8; nt++) {
            int c0 = nt * 8 + (lane & 3) * 2;
            float ma0 = madd[c0], ma1 = madd[c0 + 1];
            s[nt][0] += ma0; s[nt][1] += ma1;
            s[nt][2] += ma0; s[nt][3] += ma1;
            if (diag) {
                int kg = kt * 64 + c0;
                if (kg     > qg0)     s[nt][0] = NEG_INF;
                if (kg + 1 > qg0)     s[nt][1] = NEG_INF;
                if (kg     > qg0 + 8) s[nt][2] = NEG_INF;
                if (kg + 1 > qg0 + 8) s[nt][3] = NEG_INF;
            }
        }
        float mx0 = -1e30f, mx1 = -1e30f;
        #pragma unroll
        for (int nt = 0; nt < 8; nt++) {
            mx0 = fmaxf(mx0, fmaxf(s[nt][0], s[nt][1]));
            mx1 = fmaxf(mx1, fmaxf(s[nt][2], s[nt][3]));
        }
        mx0 = fmaxf(mx0, __shfl_xor_sync(0xffffffffu, mx0, 1));
        mx0 = fmaxf(mx0, __shfl_xor_sync(0xffffffffu, mx0, 2));
        mx1 = fmaxf(mx1, __shfl_xor_sync(0xffffffffu, mx1, 1));
        mx1 = fmaxf(mx1, __shfl_xor_sync(0xffffffffu, mx1, 2));
        float mn0 = fmaxf(m0, mx0), mn1 = fmaxf(m1, mx1);
        float a0 = __expf(m0 - mn0), a1 = __expf(m1 - mn1);
        m0 = mn0; m1 = mn1;

        float ps0 = 0.0f, ps1 = 0.0f;
        #pragma unroll
        for (int nt = 0; nt < 8; nt++) {
            s[nt][0] = __expf(s[nt][0] - mn0);
            s[nt][1] = __expf(s[nt][1] - mn0);
            s[nt][2] = __expf(s[nt][2] - mn1);
            s[nt][3] = __expf(s[nt][3] - mn1);
            ps0 += s[nt][0] + s[nt][1];
            ps1 += s[nt][2] + s[nt][3];
        }
        ps0 += __shfl_xor_sync(0xffffffffu, ps0, 1);
        ps0 += __shfl_xor_sync(0xffffffffu, ps0, 2);
        ps1 += __shfl_xor_sync(0xffffffffu, ps1, 1);
        ps1 += __shfl_xor_sync(0xffffffffu, ps1, 2);
        l0 = l0 * a0 + ps0;
        l1 = l1 * a1 + ps1;
        #pragma unroll
        for (int nt = 0; nt < 8; nt++) {
            o[nt][0] *= a0; o[nt][1] *= a0;
            o[nt][2] *= a1; o[nt][3] *= a1;
        }

        #pragma unroll
        for (int t = 0; t < 4; t++) {
            __nv_bfloat16 h0 = __float2bfloat16(s[2*t][0]);
            __nv_bfloat16 h1 = __float2bfloat16(s[2*t][1]);
            __nv_bfloat16 h2 = __float2bfloat16(s[2*t][2]);
            __nv_bfloat16 h3 = __float2bfloat16(s[2*t][3]);
            __nv_bfloat16 h4 = __float2bfloat16(s[2*t+1][0]);
            __nv_bfloat16 h5 = __float2bfloat16(s[2*t+1][1]);
            __nv_bfloat16 h6 = __float2bfloat16(s[2*t+1][2]);
            __nv_bfloat16 h7 = __float2bfloat16(s[2*t+1][3]);
            uint32_t ph[4], pl[4];
            ph[0] = packh(h0, h1);
            ph[1] = packh(h2, h3);
            ph[2] = packh(h4, h5);
            ph[3] = packh(h6, h7);
            pl[0] = packh(__float2bfloat16(s[2*t][0]   - __bfloat162float(h0)),
                          __float2bfloat16(s[2*t][1]   - __bfloat162float(h1)));
            pl[1] = packh(__float2bfloat16(s[2*t][2]   - __bfloat162float(h2)),
                          __float2bfloat16(s[2*t][3]   - __bfloat162float(h3)));
            pl[2] = packh(__float2bfloat16(s[2*t+1][0] - __bfloat162float(h4)),
                          __float2bfloat16(s[2*t+1][1] - __bfloat162float(h5)));
            pl[3] = packh(__float2bfloat16(s[2*t+1][2] - __bfloat162float(h6)),
                          __float2bfloat16(s[2*t+1][3] - __bfloat162float(h7)));

            uint32_t vh[4][4], vl[4][4];
            #pragma unroll
            for (int np = 0; np < 4; np++) {
                uint32_t voff = (uint32_t)((np * 16) * (ASTR * 2) + t * 32) + lmoff;
                ldsm_x4(vh[np], sVh_b + voff);
                ldsm_x4(vl[np], sVl_b + voff);
            }
            #pragma unroll
            for (int nt = 0; nt < 8; nt++) {
                int np = nt >> 1, od = nt & 1;
                mma_bf16(o[nt], ph, vh[np][od], vh[np][od + 2]);
            }
            #pragma unroll
            for (int nt = 0; nt < 8; nt++) {
                int np = nt >> 1, od = nt & 1;
                mma_bf16(o[nt], ph, vl[np][od], vl[np][od + 2]);
            }
            #pragma unroll
            for (int nt = 0; nt < 8; nt++) {
                int np = nt >> 1, od = nt & 1;
                mma_bf16(o[nt], pl, vh[np][od], vh[np][od + 2]);
            }
        }
        __syncthreads();
    }

    // ---- finalize + write split bf16 directly to g_xhi/g_xlo [B,S,Dm] ----
    float il0 = 1.0f / l0, il1 = 1.0f / l1;
    const int row = qt * 64 + wid * 16 + (lane >> 2);
    #pragma unroll
    for (int nt = 0; nt < 8; nt++) {
        int col = h * HD + nt * 8 + (lane & 3) * 2;
        size_t i0 = ((size_t)(b * SS) + row) * DM + col;
        size_t i1 = ((size_t)(b * SS) + row + 8) * DM + col;
        float v0 = o[nt][0] * il0, v1 = o[nt][1] * il0;
        float v2 = o[nt][2] * il1, v3 = o[nt][3] * il1;
        __nv_bfloat16 hh0 = __float2bfloat16(v0);
        __nv_bfloat16 hh1 = __float2bfloat16(v1);
        __nv_bfloat16 hh2 = __float2bfloat16(v2);
        __nv_bfloat16 hh3 = __float2bfloat16(v3);
        *(__nv_bfloat162*)&g_xhi[i0] = __nv_bfloat162(hh0, hh1);
        *(__nv_bfloat162*)&g_xhi[i1] = __nv_bfloat162(hh2, hh3);
        *(__nv_bfloat162*)&g_xlo[i0] =
            __nv_bfloat162(__float2bfloat16(v0 - __bfloat162float(hh0)),
                           __float2bfloat16(v1 - __bfloat162float(hh1)));
        *(__nv_bfloat162*)&g_xlo[i1] =
            __nv_bfloat162(__float2bfloat16(v2 - __bfloat162float(hh2)),
                           __float2bfloat16(v3 - __bfloat162float(hh3)));
    }
}

// ---------------------------------------------------------------------------
extern "C" void kernel_launch(void* const* d_in, const int* in_sizes, int n_in,
                              void* d_out, int out_size)
{
    const float* x    = (const float*)d_in[0];
    const float* mask = (const float*)d_in[1];
    const float* Wq   = (const float*)d_in[2];
    const float* Wk   = (const float*)d_in[3];
    const float* Wv   = (const float*)d_in[4];
    const float* Wo   = (const float*)d_in[5];
    float* out = (float*)d_out;

    float *tq, *tk, *tv;
    __nv_bfloat16 *xhi, *xlo, *wthi, *wtlo;
    cudaGetSymbolAddress((void**)&tq, g_tq);
    cudaGetSymbolAddress((void**)&tk, g_tk);
    cudaGetSymbolAddress((void**)&tv, g_tv);
    cudaGetSymbolAddress((void**)&xhi, g_xhi);
    cudaGetSymbolAddress((void**)&xlo, g_xlo);
    cudaGetSymbolAddress((void**)&wthi, g_wthi);
    cudaGetSymbolAddress((void**)&wtlo, g_wtlo);

    cudaFuncSetAttribute(gemm_tc_kernel,
                         cudaFuncAttributeMaxDynamicSharedMemorySize, GSM_TOTAL);

    const int M = BB * SS;   // 4096
    const int NELEM = BB * SS * DM;

    // 0) prep: input split, weight transpose+split, trig table
    split_kernel<<<NELEM / 1024, 256>>>(x, xhi, xlo);
    wsplit_kernel<<<dim3(DM / 32, DM / 32, 4), 256>>>(Wq, Wk, Wv, Wo);
    trig_kernel<<<(SS * 32) / 256, 256>>>();

    // 1) fused QKV projections (HMMA split-bf16, 4-stage pipeline)
    gemm_tc_kernel<<<dim3(DM / GBN, M / GBM, 3), 256, GSM_TOTAL>>>(
        xhi, xlo, wthi, wtlo, tq, tk, tv);

    // 2) RoPE (table-based) + transpose + split for Q,K; V transpose + split
    ropeqk_kernel<<<dim3((BB * NH * SS * 32) / 256, 2), 256>>>();
    vtrans_kernel<<<dim3(SS / 32, NH, BB), 256>>>();

    // 3) causal flash attention (HMMA split-bf16, term-major)
    attention_tc_kernel<<<dim3(SS / 64, BB * NH), 128>>>(mask);

    // 4) O projection (reads split written by attention)
    gemm_tc_kernel<<<dim3(DM / GBN, M / GBM, 1), 256, GSM_TOTAL>>>(
        xhi, xlo, wthi + 3 * (size_t)DM * DM, wtlo + 3 * (size_t)DM * DM,
        out, out, out);
}

// round 9
// speedup vs baseline: 1.0978x; 1.0279x over previous
#include <cuda_runtime.h>
#include <cuda_bf16.h>
#include <math.h>
#include <stdint.h>

#define BB 2
#define SS 2048
#define DM 1024
#define NH 16
#define HD 64
#define NEG_INF -1000000000.0f

// ---------------- scratch (device globals: allocation-free) ----------------
__device__ __nv_bfloat16 g_xhi[BB*SS*DM];       // activation split
__device__ __nv_bfloat16 g_xlo[BB*SS*DM];
__device__ __nv_bfloat16 g_wthi[4*DM*DM];       // W^T split: [z][N][K]
__device__ __nv_bfloat16 g_wtlo[4*DM*DM];

__device__ __nv_bfloat16 g_Qhi[BB*NH*SS*HD];    // [B,H,S,Hd], pre-scaled
__device__ __nv_bfloat16 g_Qlo[BB*NH*SS*HD];
__device__ __nv_bfloat16 g_Khi[BB*NH*SS*HD];
__device__ __nv_bfloat16 g_Klo[BB*NH*SS*HD];
__device__ __nv_bfloat16 g_Vthi[BB*NH*HD*SS];   // [B,H,Hd,S] (transposed)
__device__ __nv_bfloat16 g_Vtlo[BB*NH*HD*SS];

__device__ float g_cos[SS*32];
__device__ float g_sin[SS*32];

// ================= warp-MMA helpers (sm_103 base, no 'a' features) ==========
__device__ __forceinline__ uint32_t smem_u32(const void* p) {
    uint32_t a;
    asm("{ .reg .u64 t; cvta.to.shared.u64 t, %1; cvt.u32.u64 %0, t; }" : "=r"(a) : "l"(p));
    return a;
}
__device__ __forceinline__ void ldsm_x4(uint32_t* r, uint32_t addr) {
    asm volatile("ldmatrix.sync.aligned.m8n8.x4.shared.b16 {%0,%1,%2,%3}, [%4];"
                 : "=r"(r[0]), "=r"(r[1]), "=r"(r[2]), "=r"(r[3]) : "r"(addr));
}
__device__ __forceinline__ void mma_bf16(float* c, const uint32_t* a,
                                         uint32_t b0, uint32_t b1) {
    asm volatile(
        "mma.sync.aligned.m16n8k16.row.col.f32.bf16.bf16.f32 "
        "{%0,%1,%2,%3}, {%4,%5,%6,%7}, {%8,%9}, {%0,%1,%2,%3};"
        : "+f"(c[0]), "+f"(c[1]), "+f"(c[2]), "+f"(c[3])
        : "r"(a[0]), "r"(a[1]), "r"(a[2]), "r"(a[3]), "r"(b0), "r"(b1));
}
__device__ __forceinline__ uint32_t packh(__nv_bfloat16 a, __nv_bfloat16 b) {
    return ((uint32_t)__bfloat16_as_ushort(b) << 16) | (uint32_t)__bfloat16_as_ushort(a);
}
__device__ __forceinline__ void cp_async16(uint32_t saddr, const void* gaddr) {
    asm volatile("cp.async.cg.shared.global [%0], [%1], 16;"
                 :: "r"(saddr), "l"(gaddr) : "memory");
}
__device__ __forceinline__ void cp_commit() {
    asm volatile("cp.async.commit_group;" ::: "memory");
}
template<int N> __device__ __forceinline__ void cp_wait() {
    asm volatile("cp.async.wait_group %0;" :: "n"(N) : "memory");
}

// ================= split / weight-prep kernels ==============================
__global__ __launch_bounds__(256)
void split_kernel(const float* __restrict__ src,
                  __nv_bfloat16* __restrict__ hi,
                  __nv_bfloat16* __restrict__ lo)
{
    int i = (blockIdx.x * 256 + threadIdx.x) * 4;
    float4 v = *(const float4*)&src[i];
    __nv_bfloat16 h0 = __float2bfloat16(v.x);
    __nv_bfloat16 h1 = __float2bfloat16(v.y);
    __nv_bfloat16 h2 = __float2bfloat16(v.z);
    __nv_bfloat16 h3 = __float2bfloat16(v.w);
    __nv_bfloat16 l0 = __float2bfloat16(v.x - __bfloat162float(h0));
    __nv_bfloat16 l1 = __float2bfloat16(v.y - __bfloat162float(h1));
    __nv_bfloat16 l2 = __float2bfloat16(v.z - __bfloat162float(h2));
    __nv_bfloat16 l3 = __float2bfloat16(v.w - __bfloat162float(h3));
    *(__nv_bfloat162*)&hi[i]     = __nv_bfloat162(h0, h1);
    *(__nv_bfloat162*)&hi[i + 2] = __nv_bfloat162(h2, h3);
    *(__nv_bfloat162*)&lo[i]     = __nv_bfloat162(l0, l1);
    *(__nv_bfloat162*)&lo[i + 2] = __nv_bfloat162(l2, l3);
}

__global__ __launch_bounds__(256)
void wsplit_kernel(const float* __restrict__ Wq, const float* __restrict__ Wk,
                   const float* __restrict__ Wv, const float* __restrict__ Wo)
{
    __shared__ float tile[32][33];
    int z = blockIdx.z;
    const float* __restrict__ W = (z == 0) ? Wq : ((z == 1) ? Wk : ((z == 2) ? Wv : Wo));
    int n0 = blockIdx.x * 32;
    int k0 = blockIdx.y * 32;
    int tx = threadIdx.x & 31;
    int ty = threadIdx.x >> 5;
    #pragma unroll
    for (int i = 0; i < 4; i++) {
        int k = ty + i * 8;
        tile[k][tx] = W[(size_t)(k0 + k) * DM + n0 + tx];
    }
    __syncthreads();
    #pragma unroll
    for (int i = 0; i < 4; i++) {
        int n = ty + i * 8;
        float v = tile[tx][n];
        __nv_bfloat16 h = __float2bfloat16(v);
        __nv_bfloat16 l = __float2bfloat16(v - __bfloat162float(h));
        size_t di = ((size_t)z * DM + n0 + n) * DM + k0 + tx;
        g_wthi[di] = h;
        g_wtlo[di] = l;
    }
}

// ---------------- trig table (double precision, tiny) ----------------------
__global__ __launch_bounds__(256)
void trig_kernel()
{
    int idx = blockIdx.x * 256 + threadIdx.x;   // [0, SS*32)
    int s = idx >> 5, j = idx & 31;
    double inv = exp(-(double)j * (9.210340371976184 / 32.0));
    double ang = (double)s * inv;
    double sn, cs;
    sincos(ang, &sn, &cs);
    g_cos[idx] = (float)cs;
    g_sin[idx] = (float)sn;
}

// ================= HMMA split-bf16 GEMM (4-stage cp.async, frag dbuf) =======
// mode 0: plain fp32 epilogue to C (O projection)
// mode 1: fused QKV epilogue — blockIdx.z: 0=Q (rope+scale), 1=K (rope), 2=V (transpose)
#define GBM 128
#define GBN 128
#define GBK 32
#define GSTR 40
#define STB (GBM * GSTR * 2)          // bytes per array = 10240
#define STAGE_B (4 * STB)             // 40960 per stage
#define GSTAGES 4
#define GSM_TOTAL (GSTAGES * STAGE_B) // 163840 (also covers 128x133 fp32 tile = 68096)
#define FSTR 133                      // fp32 epilogue tile stride (conflict-free)

__device__ __forceinline__ void load_frags(
    uint32_t ah[4][4], uint32_t al[4][4], uint32_t bh[2][4], uint32_t bl[2][4],
    uint32_t st, int ks, int wm, int wn, uint32_t lmoff)
{
    const uint32_t sAh = st, sAl = st + STB, sBh = st + 2 * STB, sBl = st + 3 * STB;
    #pragma unroll
    for (int mt = 0; mt < 4; mt++) {
        uint32_t aoff = (uint32_t)((wm * 64 + mt * 16) * (GSTR * 2) + ks * 32) + lmoff;
        ldsm_x4(ah[mt], sAh + aoff);
        ldsm_x4(al[mt], sAl + aoff);
    }
    #pragma unroll
    for (int nt2 = 0; nt2 < 2; nt2++) {
        uint32_t boff = (uint32_t)((wn * 32 + nt2 * 16) * (GSTR * 2) + ks * 32) + lmoff;
        ldsm_x4(bh[nt2], sBh + boff);
        ldsm_x4(bl[nt2], sBl + boff);
    }
}

__device__ __forceinline__ void mma_all(
    float acc[4][4][4],
    uint32_t ah[4][4], uint32_t al[4][4], uint32_t bh[2][4], uint32_t bl[2][4])
{
    #pragma unroll
    for (int mt = 0; mt < 4; mt++)
        #pragma unroll
        for (int nt = 0; nt < 4; nt++) {
            int n2 = nt >> 1, od = nt & 1;
            mma_bf16(acc[mt][nt], ah[mt], bh[n2][od], bh[n2][od + 2]);
        }
    #pragma unroll
    for (int mt = 0; mt < 4; mt++)
        #pragma unroll
        for (int nt = 0; nt < 4; nt++) {
            int n2 = nt >> 1, od = nt & 1;
            mma_bf16(acc[mt][nt], ah[mt], bl[n2][od], bl[n2][od + 2]);
        }
    #pragma unroll
    for (int mt = 0; mt < 4; mt++)
        #pragma unroll
        for (int nt = 0; nt < 4; nt++) {
            int n2 = nt >> 1, od = nt & 1;
            mma_bf16(acc[mt][nt], al[mt], bh[n2][od], bh[n2][od + 2]);
        }
}

__global__ __launch_bounds__(256)
void gemm_tc_kernel(const __nv_bfloat16* __restrict__ Ahi,
                    const __nv_bfloat16* __restrict__ Alo,
                    const __nv_bfloat16* __restrict__ Whi,
                    const __nv_bfloat16* __restrict__ Wlo,
                    float* __restrict__ C, int mode)
{
    extern __shared__ __align__(16) char dsm[];

    const int tid  = threadIdx.x;
    const int wid  = tid >> 5;
    const int lane = tid & 31;
    const int m0 = blockIdx.y * GBM;
    const int n0 = blockIdx.x * GBN;
    const int z  = blockIdx.z;
    const __nv_bfloat16* __restrict__ Wh = Whi + (size_t)z * DM * DM;
    const __nv_bfloat16* __restrict__ Wl = Wlo + (size_t)z * DM * DM;

    const int wm = wid & 1;
    const int wn = wid >> 1;

    const int row_off = (lane & 7) + ((lane >> 3) & 1) * 8;
    const int kadd    = ((lane >> 4) & 1) * 8;
    const uint32_t lmoff = (uint32_t)(row_off * (GSTR * 2) + kadd * 2);

    const uint32_t sbase = smem_u32(dsm);
    const int r_a = tid >> 2;
    const int c_a = tid & 3;
    const uint32_t so0 = (uint32_t)(r_a * (GSTR * 2) + c_a * 16);
    const uint32_t so1 = (uint32_t)((r_a + 64) * (GSTR * 2) + c_a * 16);

    float acc[4][4][4];
    #pragma unroll
    for (int i = 0; i < 4; i++)
        #pragma unroll
        for (int j = 0; j < 4; j++)
            #pragma unroll
            for (int q = 0; q < 4; q++) acc[i][j][q] = 0.0f;

    const int NK = DM / GBK;   // 32

    auto issue_cp = [&](int kcc) {
        const int k0 = kcc * GBK;
        uint32_t s0 = sbase + (uint32_t)((kcc % GSTAGES) * STAGE_B);
        size_t ga0 = (size_t)(m0 + r_a) * DM + k0 + c_a * 8;
        size_t ga1 = (size_t)(m0 + r_a + 64) * DM + k0 + c_a * 8;
        size_t gb0 = (size_t)(n0 + r_a) * DM + k0 + c_a * 8;
        size_t gb1 = (size_t)(n0 + r_a + 64) * DM + k0 + c_a * 8;
        cp_async16(s0 + so0,           &Ahi[ga0]);
        cp_async16(s0 + so1,           &Ahi[ga1]);
        cp_async16(s0 + STB + so0,     &Alo[ga0]);
        cp_async16(s0 + STB + so1,     &Alo[ga1]);
        cp_async16(s0 + 2*STB + so0,   &Wh[gb0]);
        cp_async16(s0 + 2*STB + so1,   &Wh[gb1]);
        cp_async16(s0 + 3*STB + so0,   &Wl[gb0]);
        cp_async16(s0 + 3*STB + so1,   &Wl[gb1]);
        cp_commit();
    };

    issue_cp(0);
    issue_cp(1);
    issue_cp(2);
    cp_wait<1>();
    __syncthreads();

    uint32_t ahC[4][4], alC[4][4], bhC[2][4], blC[2][4];
    uint32_t ahN[4][4], alN[4][4], bhN[2][4], blN[2][4];

    load_frags(ahC, alC, bhC, blC, sbase, 0, wm, wn, lmoff);

    for (int kc = 0; kc < NK; kc++) {
        const uint32_t stC = sbase + (uint32_t)((kc % GSTAGES) * STAGE_B);
        const uint32_t stN = sbase + (uint32_t)(((kc + 1) % GSTAGES) * STAGE_B);

        load_frags(ahN, alN, bhN, blN, stC, 1, wm, wn, lmoff);
        mma_all(acc, ahC, alC, bhC, blC);

        if (kc + 1 < NK)
            load_frags(ahC, alC, bhC, blC, stN, 0, wm, wn, lmoff);
        mma_all(acc, ahN, alN, bhN, blN);

        if (kc + 3 < NK) {
            issue_cp(kc + 3);
            cp_wait<1>();
        } else {
            cp_wait<0>();
        }
        __syncthreads();
    }

    const int g   = lane >> 2;
    const int tig = lane & 3;

    if (mode == 0) {
        // plain epilogue (O projection)
        #pragma unroll
        for (int mt = 0; mt < 4; mt++) {
            int row = m0 + wm * 64 + mt * 16 + g;
            #pragma unroll
            for (int nt = 0; nt < 4; nt++) {
                int col = n0 + wn * 32 + nt * 8 + tig * 2;
                *(float2*)&C[(size_t)row * DM + col]       = make_float2(acc[mt][nt][0], acc[mt][nt][1]);
                *(float2*)&C[(size_t)(row + 8) * DM + col] = make_float2(acc[mt][nt][2], acc[mt][nt][3]);
            }
        }
        return;
    }

    // ---- fused QKV epilogue: stage acc tile to smem fp32 ----
    float* ftile = (float*)dsm;
    #pragma unroll
    for (int mt = 0; mt < 4; mt++) {
        int r = wm * 64 + mt * 16 + g;
        #pragma unroll
        for (int nt = 0; nt < 4; nt++) {
            int c = wn * 32 + nt * 8 + tig * 2;
            ftile[r * FSTR + c]           = acc[mt][nt][0];
            ftile[r * FSTR + c + 1]       = acc[mt][nt][1];
            ftile[(r + 8) * FSTR + c]     = acc[mt][nt][2];
            ftile[(r + 8) * FSTR + c + 1] = acc[mt][nt][3];
        }
    }
    __syncthreads();

    if (z == 2) {
        // V: transpose + split -> g_Vt* [B,H,Hd,S]
        int r = tid & 127;
        int row = m0 + r;
        int b = row >> 11;
        int s = row & (SS - 1);
        int cbase = (tid >> 7) * 64;       // 0 or 64
        #pragma unroll 8
        for (int i = 0; i < 64; i++) {
            int c = cbase + i;
            float v = ftile[r * FSTR + c];
            int col = n0 + c;
            int h = col >> 6;
            int jv = col & 63;
            __nv_bfloat16 hh = __float2bfloat16(v);
            __nv_bfloat16 ll = __float2bfloat16(v - __bfloat162float(hh));
            size_t di = ((size_t)(b * NH + h) * HD + jv) * SS + s;
            g_Vthi[di] = hh;
            g_Vtlo[di] = ll;
        }
    } else {
        // Q/K: rope + (scale) + split -> g_Q*/g_K* [B,H,S,Hd]
        const float scale = (z == 0) ? 0.125f : 1.0f;
        __nv_bfloat16* __restrict__ dhi = (z == 0) ? g_Qhi : g_Khi;
        __nv_bfloat16* __restrict__ dlo = (z == 0) ? g_Qlo : g_Klo;
        int pc = tid & 63;                 // pair-col within 2 heads
        int h2 = pc >> 5;
        int j  = pc & 31;
        int c1 = h2 * 64 + j;
        int c2 = c1 + 32;
        int h = (n0 + c1) >> 6;
        #pragma unroll 8
        for (int i = 0; i < 32; i++) {
            int r = (tid >> 6) + i * 4;
            int row = m0 + r;
            int b = row >> 11;
            int s = row & (SS - 1);
            float t1 = ftile[r * FSTR + c1];
            float t2 = ftile[r * FSTR + c2];
            float cs = g_cos[s * 32 + j];
            float sn = g_sin[s * 32 + j];
            float o1 = (t1 * cs - t2 * sn) * scale;
            float o2 = (t1 * sn + t2 * cs) * scale;
            __nv_bfloat16 h1 = __float2bfloat16(o1);
            __nv_bfloat16 hb2 = __float2bfloat16(o2);
            __nv_bfloat16 l1 = __float2bfloat16(o1 - __bfloat162float(h1));
            __nv_bfloat16 l2 = __float2bfloat16(o2 - __bfloat162float(hb2));
            size_t di = (((size_t)(b * NH + h)) * SS + s) * HD;
            dhi[di + j]      = h1;
            dhi[di + 32 + j] = hb2;
            dlo[di + j]      = l1;
            dlo[di + 32 + j] = l2;
        }
    }
}

// ---------------- HMMA split-bf16 flash attention (term-major) --------------
#define ASTR 72

__global__ __launch_bounds__(128)
void attention_tc_kernel(const float* __restrict__ mask)
{
    __shared__ __align__(16) __nv_bfloat16 sKh[64 * ASTR];
    __shared__ __align__(16) __nv_bfloat16 sKl[64 * ASTR];
    __shared__ __align__(16) __nv_bfloat16 sVh[64 * ASTR];
    __shared__ __align__(16) __nv_bfloat16 sVl[64 * ASTR];
    __shared__ float madd[64];

    const int tid  = threadIdx.x;
    const int wid  = tid >> 5;
    const int lane = tid & 31;
    const int qt = gridDim.x - 1 - blockIdx.x;
    const int bh = blockIdx.y;
    const int b  = bh >> 4;
    const int h  = bh & 15;

    const size_t baseqk = (size_t)bh * SS * HD;
    const size_t basev  = (size_t)bh * HD * SS;

    const int row_off = (lane & 7) + ((lane >> 3) & 1) * 8;
    const int kadd    = ((lane >> 4) & 1) * 8;
    const uint32_t lmoff = (uint32_t)(row_off * (ASTR * 2) + kadd * 2);

    const uint32_t sKh_b = smem_u32(sKh), sKl_b = smem_u32(sKl);
    const uint32_t sVh_b = smem_u32(sVh), sVl_b = smem_u32(sVl);

    #pragma unroll
    for (int i = 0; i < 4; i++) {
        int idx = tid + i * 128;
        int r = idx >> 3, c8 = idx & 7;
        uint32_t so = (uint32_t)(r * (ASTR * 2) + c8 * 16);
        size_t gi = baseqk + (size_t)(qt * 64 + r) * HD + c8 * 8;
        *(uint4*)((char*)sKh + so) = *(const uint4*)&g_Qhi[gi];
        *(uint4*)((char*)sKl + so) = *(const uint4*)&g_Qlo[gi];
    }
    __syncthreads();
    uint32_t qh[4][4], ql[4][4];
    #pragma unroll
    for (int kc = 0; kc < 4; kc++) {
        uint32_t aoff = (uint32_t)((wid * 16) * (ASTR * 2) + kc * 32) + lmoff;
        ldsm_x4(qh[kc], sKh_b + aoff);
        ldsm_x4(ql[kc], sKl_b + aoff);
    }
    __syncthreads();

    float o[8][4];
    #pragma unroll
    for (int nt = 0; nt < 8; nt++)
        #pragma unroll
        for (int q = 0; q < 4; q++) o[nt][q] = 0.0f;
    float m0 = -1e30f, m1 = -1e30f, l0 = 0.0f, l1 = 0.0f;

    const int qg0 = qt * 64 + wid * 16 + (lane >> 2);

    for (int kt = 0; kt <= qt; kt++) {
        #pragma unroll
        for (int i = 0; i < 4; i++) {
            int idx = tid + i * 128;
            int r = idx >> 3, c8 = idx & 7;
            uint32_t so = (uint32_t)(r * (ASTR * 2) + c8 * 16);
            size_t gk = baseqk + (size_t)(kt * 64 + r) * HD + c8 * 8;
            size_t gv = basev + (size_t)r * SS + kt * 64 + c8 * 8;
            *(uint4*)((char*)sKh + so) = *(const uint4*)&g_Khi[gk];
            *(uint4*)((char*)sKl + so) = *(const uint4*)&g_Klo[gk];
            *(uint4*)((char*)sVh + so) = *(const uint4*)&g_Vthi[gv];
            *(uint4*)((char*)sVl + so) = *(const uint4*)&g_Vtlo[gv];
        }
        if (tid < 64) {
            float mv = mask[b * SS + kt * 64 + tid];
            madd[tid] = (1.0f - mv) * NEG_INF;
        }
        __syncthreads();

        float s[8][4];
        #pragma unroll
        for (int nt = 0; nt < 8; nt++)
            #pragma unroll
            for (int q = 0; q < 4; q++) s[nt][q] = 0.0f;

        #pragma unroll
        for (int kc = 0; kc < 4; kc++) {
            uint32_t kh[4][4], kl[4][4];
            #pragma unroll
            for (int np = 0; np < 4; np++) {
                uint32_t boff = (uint32_t)((np * 16) * (ASTR * 2) + kc * 32) + lmoff;
                ldsm_x4(kh[np], sKh_b + boff);
                ldsm_x4(kl[np], sKl_b + boff);
            }
            #pragma unroll
            for (int nt = 0; nt < 8; nt++) {
                int np = nt >> 1, od = nt & 1;
                mma_bf16(s[nt], qh[kc], kh[np][od], kh[np][od + 2]);
            }
            #pragma unroll
            for (int nt = 0; nt < 8; nt++) {
                int np = nt >> 1, od = nt & 1;
                mma_bf16(s[nt], qh[kc], kl[np][od], kl[np][od + 2]);
            }
            #pragma unroll
            for (int nt = 0; nt < 8; nt++) {
                int np = nt >> 1, od = nt & 1;
                mma_bf16(s[nt], ql[kc], kh[np][od], kh[np][od + 2]);
            }
        }

        const bool diag = (kt == qt);
        #pragma unroll
        for (int nt = 0; nt < 8; nt++) {
            int c0 = nt * 8 + (lane & 3) * 2;
            float ma0 = madd[c0], ma1 = madd[c0 + 1];
            s[nt][0] += ma0; s[nt][1] += ma1;
            s[nt][2] += ma0; s[nt][3] += ma1;
            if (diag) {
                int kg = kt * 64 + c0;
                if (kg     > qg0)     s[nt][0] = NEG_INF;
                if (kg + 1 > qg0)     s[nt][1] = NEG_INF;
                if (kg     > qg0 + 8) s[nt][2] = NEG_INF;
                if (kg + 1 > qg0 + 8) s[nt][3] = NEG_INF;
            }
        }
        float mx0 = -1e30f, mx1 = -1e30f;
        #pragma unroll
        for (int nt = 0; nt < 8; nt++) {
            mx0 = fmaxf(mx0, fmaxf(s[nt][0], s[nt][1]));
            mx1 = fmaxf(mx1, fmaxf(s[nt][2], s[nt][3]));
        }
        mx0 = fmaxf(mx0, __shfl_xor_sync(0xffffffffu, mx0, 1));
        mx0 = fmaxf(mx0, __shfl_xor_sync(0xffffffffu, mx0, 2));
        mx1 = fmaxf(mx1, __shfl_xor_sync(0xffffffffu, mx1, 1));
        mx1 = fmaxf(mx1, __shfl_xor_sync(0xffffffffu, mx1, 2));
        float mn0 = fmaxf(m0, mx0), mn1 = fmaxf(m1, mx1);
        float a0 = __expf(m0 - mn0), a1 = __expf(m1 - mn1);
        m0 = mn0; m1 = mn1;

        float ps0 = 0.0f, ps1 = 0.0f;
        #pragma unroll
        for (int nt = 0; nt < 8; nt++) {
            s[nt][0] = __expf(s[nt][0] - mn0);
            s[nt][1] = __expf(s[nt][1] - mn0);
            s[nt][2] = __expf(s[nt][2] - mn1);
            s[nt][3] = __expf(s[nt][3] - mn1);
            ps0 += s[nt][0] + s[nt][1];
            ps1 += s[nt][2] + s[nt][3];
        }
        ps0 += __shfl_xor_sync(0xffffffffu, ps0, 1);
        ps0 += __shfl_xor_sync(0xffffffffu, ps0, 2);
        ps1 += __shfl_xor_sync(0xffffffffu, ps1, 1);
        ps1 += __shfl_xor_sync(0xffffffffu, ps1, 2);
        l0 = l0 * a0 + ps0;
        l1 = l1 * a1 + ps1;
        #pragma unroll
        for (int nt = 0; nt < 8; nt++) {
            o[nt][0] *= a0; o[nt][1] *= a0;
            o[nt][2] *= a1; o[nt][3] *= a1;
        }

        #pragma unroll
        for (int t = 0; t < 4; t++) {
            __nv_bfloat16 h0 = __float2bfloat16(s[2*t][0]);
            __nv_bfloat16 h1 = __float2bfloat16(s[2*t][1]);
            __nv_bfloat16 h2 = __float2bfloat16(s[2*t][2]);
            __nv_bfloat16 h3 = __float2bfloat16(s[2*t][3]);
            __nv_bfloat16 h4 = __float2bfloat16(s[2*t+1][0]);
            __nv_bfloat16 h5 = __float2bfloat16(s[2*t+1][1]);
            __nv_bfloat16 h6 = __float2bfloat16(s[2*t+1][2]);
            __nv_bfloat16 h7 = __float2bfloat16(s[2*t+1][3]);
            uint32_t ph[4], pl[4];
            ph[0] = packh(h0, h1);
            ph[1] = packh(h2, h3);
            ph[2] = packh(h4, h5);
            ph[3] = packh(h6, h7);
            pl[0] = packh(__float2bfloat16(s[2*t][0]   - __bfloat162float(h0)),
                          __float2bfloat16(s[2*t][1]   - __bfloat162float(h1)));
            pl[1] = packh(__float2bfloat16(s[2*t][2]   - __bfloat162float(h2)),
                          __float2bfloat16(s[2*t][3]   - __bfloat162float(h3)));
            pl[2] = packh(__float2bfloat16(s[2*t+1][0] - __bfloat162float(h4)),
                          __float2bfloat16(s[2*t+1][1] - __bfloat162float(h5)));
            pl[3] = packh(__float2bfloat16(s[2*t+1][2] - __bfloat162float(h6)),
                          __float2bfloat16(s[2*t+1][3] - __bfloat162float(h7)));

            uint32_t vh[4][4], vl[4][4];
            #pragma unroll
            for (int np = 0; np < 4; np++) {
                uint32_t voff = (uint32_t)((np * 16) * (ASTR * 2) + t * 32) + lmoff;
                ldsm_x4(vh[np], sVh_b + voff);
                ldsm_x4(vl[np], sVl_b + voff);
            }
            #pragma unroll
            for (int nt = 0; nt < 8; nt++) {
                int np = nt >> 1, od = nt & 1;
                mma_bf16(o[nt], ph, vh[np][od], vh[np][od + 2]);
            }
            #pragma unroll
            for (int nt = 0; nt < 8; nt++) {
                int np = nt >> 1, od = nt & 1;
                mma_bf16(o[nt], ph, vl[np][od], vl[np][od + 2]);
            }
            #pragma unroll
            for (int nt = 0; nt < 8; nt++) {
                int np = nt >> 1, od = nt & 1;
                mma_bf16(o[nt], pl, vh[np][od], vh[np][od + 2]);
            }
        }
        __syncthreads();
    }

    // ---- finalize + write split bf16 directly to g_xhi/g_xlo [B,S,Dm] ----
    float il0 = 1.0f / l0, il1 = 1.0f / l1;
    const int row = qt * 64 + wid * 16 + (lane >> 2);
    #pragma unroll
    for (int nt = 0; nt < 8; nt++) {
        int col = h * HD + nt * 8 + (lane & 3) * 2;
        size_t i0 = ((size_t)(b * SS) + row) * DM + col;
        size_t i1 = ((size_t)(b * SS) + row + 8) * DM + col;
        float v0 = o[nt][0] * il0, v1 = o[nt][1] * il0;
        float v2 = o[nt][2] * il1, v3 = o[nt][3] * il1;
        __nv_bfloat16 hh0 = __float2bfloat16(v0);
        __nv_bfloat16 hh1 = __float2bfloat16(v1);
        __nv_bfloat16 hh2 = __float2bfloat16(v2);
        __nv_bfloat16 hh3 = __float2bfloat16(v3);
        *(__nv_bfloat162*)&g_xhi[i0] = __nv_bfloat162(hh0, hh1);
        *(__nv_bfloat162*)&g_xhi[i1] = __nv_bfloat162(hh2, hh3);
        *(__nv_bfloat162*)&g_xlo[i0] =
            __nv_bfloat162(__float2bfloat16(v0 - __bfloat162float(hh0)),
                           __float2bfloat16(v1 - __bfloat162float(hh1)));
        *(__nv_bfloat162*)&g_xlo[i1] =
            __nv_bfloat162(__float2bfloat16(v2 - __bfloat162float(hh2)),
                           __float2bfloat16(v3 - __bfloat162float(hh3)));
    }
}

// ---------------------------------------------------------------------------
extern "C" void kernel_launch(void* const* d_in, const int* in_sizes, int n_in,
                              void* d_out, int out_size)
{
    const float* x    = (const float*)d_in[0];
    const float* mask = (const float*)d_in[1];
    const float* Wq   = (const float*)d_in[2];
    const float* Wk   = (const float*)d_in[3];
    const float* Wv   = (const float*)d_in[4];
    const float* Wo   = (const float*)d_in[5];
    float* out = (float*)d_out;

    __nv_bfloat16 *xhi, *xlo, *wthi, *wtlo;
    cudaGetSymbolAddress((void**)&xhi, g_xhi);
    cudaGetSymbolAddress((void**)&xlo, g_xlo);
    cudaGetSymbolAddress((void**)&wthi, g_wthi);
    cudaGetSymbolAddress((void**)&wtlo, g_wtlo);

    cudaFuncSetAttribute(gemm_tc_kernel,
                         cudaFuncAttributeMaxDynamicSharedMemorySize, GSM_TOTAL);

    const int M = BB * SS;   // 4096
    const int NELEM = BB * SS * DM;

    // 0) prep: input split, weight transpose+split, trig table
    split_kernel<<<NELEM / 1024, 256>>>(x, xhi, xlo);
    wsplit_kernel<<<dim3(DM / 32, DM / 32, 4), 256>>>(Wq, Wk, Wv, Wo);
    trig_kernel<<<(SS * 32) / 256, 256>>>();

    // 1) fused QKV projections + RoPE/transpose/split epilogue
    gemm_tc_kernel<<<dim3(DM / GBN, M / GBM, 3), 256, GSM_TOTAL>>>(
        xhi, xlo, wthi, wtlo, nullptr, 1);

    // 2) causal flash attention (HMMA split-bf16), writes split output
    attention_tc_kernel<<<dim3(SS / 64, BB * NH), 128>>>(mask);

    // 3) O projection (reads split written by attention)
    gemm_tc_kernel<<<dim3(DM / GBN, M / GBM, 1), 256, GSM_TOTAL>>>(
        xhi, xlo, wthi + 3 * (size_t)DM * DM, wtlo + 3 * (size_t)DM * DM,
        out, 0);
}